// round 7
// baseline (speedup 1.0000x reference)
#include <cuda_runtime.h>
#include <math.h>

#define B_  2
#define S_  2048
#define DM  1024
#define NH  16
#define DK  64
#define WIN 512

// Scratch (allocation-free rule: __device__ globals)
__device__ float g_q[B_*NH*S_*DK];      // [B,H,S,Dk]
__device__ float g_k[B_*NH*S_*DK];
__device__ float g_v[B_*NH*S_*DK];
__device__ float g_attn[B_*S_*DM];      // [B,S,D]

// ---------------------------------------------------------------------------
// SGEMM: 128x128 block tile, BK=16, 256 threads, 8x8 register tile,
// double-buffered smem. A via LDG->reg->transposed STS, B via cp.async.
// ---------------------------------------------------------------------------
#define BM 128
#define BN 128
#define BK 16
#define AS_STRIDE (BM + 4)   // pad: STS transpose conflicts 4-way -> 2-way,
                             // keeps rows 16B-aligned (132*4 = 528B)

__device__ __forceinline__ unsigned smem_u32(const void* p) {
    return (unsigned)__cvta_generic_to_shared(p);
}
#define CP_ASYNC16(dst_u32, src_ptr) \
    asm volatile("cp.async.cg.shared.global [%0], [%1], 16;\n" :: "r"(dst_u32), "l"(src_ptr))
#define CP_COMMIT() asm volatile("cp.async.commit_group;\n" ::: "memory")
#define CP_WAIT0()  asm volatile("cp.async.wait_group 0;\n" ::: "memory")

// Shared GEMM mainloop: computes acc[8][8] for C tile (m0,n0).
// A is MxK row-major (K = DM), B is KxN row-major.
template<int N>
__device__ __forceinline__ void sgemm_mainloop(
    const float* __restrict__ A, const float* __restrict__ Bm,
    int m0, int n0, float acc[8][8],
    float (*As)[BK][AS_STRIDE], float (*Bs)[BK][BN])
{
    const int K = DM;
    const int tid = threadIdx.x;
    const int tx = tid & 15;
    const int ty = tid >> 4;

    // per-thread load coords (2 chunks each for A and B)
    const int a_row0 = tid >> 2;                 // 0..63
    const int a_row1 = a_row0 + 64;              // 64..127
    const int a_c4   = (tid & 3) << 2;           // 0,4,8,12
    const int b_r0   = tid >> 5;                 // 0..7
    const int b_r1   = b_r0 + 8;                 // 8..15
    const int b_c4   = (tid & 31) << 2;          // 0..124

    // ---- prologue: tile kt=0 into buffer 0 ----
    {
        float4 pa0 = *(const float4*)(A + (size_t)(m0 + a_row0) * K + a_c4);
        float4 pa1 = *(const float4*)(A + (size_t)(m0 + a_row1) * K + a_c4);
        As[0][a_c4 + 0][a_row0] = pa0.x;
        As[0][a_c4 + 1][a_row0] = pa0.y;
        As[0][a_c4 + 2][a_row0] = pa0.z;
        As[0][a_c4 + 3][a_row0] = pa0.w;
        As[0][a_c4 + 0][a_row1] = pa1.x;
        As[0][a_c4 + 1][a_row1] = pa1.y;
        As[0][a_c4 + 2][a_row1] = pa1.z;
        As[0][a_c4 + 3][a_row1] = pa1.w;
        CP_ASYNC16(smem_u32(&Bs[0][b_r0][b_c4]), Bm + (size_t)b_r0 * N + n0 + b_c4);
        CP_ASYNC16(smem_u32(&Bs[0][b_r1][b_c4]), Bm + (size_t)b_r1 * N + n0 + b_c4);
        CP_COMMIT();
        CP_WAIT0();
        __syncthreads();
    }

    int buf = 0;
    for (int kt = 0; kt < K; kt += BK, buf ^= 1) {
        const int nxt = kt + BK;
        float4 pa0, pa1;
        if (nxt < K) {
            // issue next-tile loads early; LDG latency hidden by compute below
            pa0 = *(const float4*)(A + (size_t)(m0 + a_row0) * K + nxt + a_c4);
            pa1 = *(const float4*)(A + (size_t)(m0 + a_row1) * K + nxt + a_c4);
            CP_ASYNC16(smem_u32(&Bs[buf ^ 1][b_r0][b_c4]),
                       Bm + (size_t)(nxt + b_r0) * N + n0 + b_c4);
            CP_ASYNC16(smem_u32(&Bs[buf ^ 1][b_r1][b_c4]),
                       Bm + (size_t)(nxt + b_r1) * N + n0 + b_c4);
            CP_COMMIT();
        }

        // ---- compute on current buffer ----
        #pragma unroll
        for (int kk = 0; kk < BK; kk++) {
            float a[8], b[8];
            *(float4*)(a)     = *(float4*)&As[buf][kk][ty * 8];
            *(float4*)(a + 4) = *(float4*)&As[buf][kk][ty * 8 + 4];
            *(float4*)(b)     = *(float4*)&Bs[buf][kk][tx * 8];
            *(float4*)(b + 4) = *(float4*)&Bs[buf][kk][tx * 8 + 4];
            #pragma unroll
            for (int i = 0; i < 8; i++)
                #pragma unroll
                for (int j = 0; j < 8; j++)
                    acc[i][j] += a[i] * b[j];
        }

        if (nxt < K) {
            const int nb = buf ^ 1;
            As[nb][a_c4 + 0][a_row0] = pa0.x;
            As[nb][a_c4 + 1][a_row0] = pa0.y;
            As[nb][a_c4 + 2][a_row0] = pa0.z;
            As[nb][a_c4 + 3][a_row0] = pa0.w;
            As[nb][a_c4 + 0][a_row1] = pa1.x;
            As[nb][a_c4 + 1][a_row1] = pa1.y;
            As[nb][a_c4 + 2][a_row1] = pa1.z;
            As[nb][a_c4 + 3][a_row1] = pa1.w;
            CP_WAIT0();
        }
        __syncthreads();
    }
}

// Kernel 1: qkv = x @ w_qkv with fused RoPE epilogue scattering into g_q/g_k/g_v
__global__ __launch_bounds__(256, 2)
void qkv_gemm_rope(const float* __restrict__ A, const float* __restrict__ Bm) {
    __shared__ float As[2][BK][AS_STRIDE];
    __shared__ float Bs[2][BK][BN];

    const int tid = threadIdx.x;
    const int tx = tid & 15;
    const int ty = tid >> 4;
    const int m0 = blockIdx.y * BM;
    const int n0 = blockIdx.x * BN;

    float acc[8][8];
    #pragma unroll
    for (int i = 0; i < 8; i++)
        #pragma unroll
        for (int j = 0; j < 8; j++) acc[i][j] = 0.f;

    sgemm_mainloop<3 * DM>(A, Bm, m0, n0, acc, As, Bs);

    // Epilogue: scatter into q/k/v with RoPE on q,k
    const int nb    = n0 + tx * 8;          // 8 consecutive cols, 8-aligned
    const int which = nb >> 10;             // 0=q 1=k 2=v (constant per block)
    const int h     = (nb & 1023) >> 6;
    const int d0    = nb & 63;              // even, multiple of 8

    if (which == 2) {
        #pragma unroll
        for (int i = 0; i < 8; i++) {
            int m = m0 + ty * 8 + i;
            int b = m >> 11, s = m & 2047;
            float* dst = g_v + (((b * NH + h) * S_ + s) * DK + d0);
            #pragma unroll
            for (int j = 0; j < 8; j++) dst[j] = acc[i][j];
        }
    } else {
        float* base = (which == 0) ? g_q : g_k;
        float invf[4];
        #pragma unroll
        for (int p = 0; p < 4; p++) {
            float t = (float)((d0 >> 1) + p);
            invf[p] = powf(10000.0f, -t / 32.0f);
        }
        #pragma unroll
        for (int i = 0; i < 8; i++) {
            int m = m0 + ty * 8 + i;
            int b = m >> 11, s = m & 2047;
            float* dst = base + (((b * NH + h) * S_ + s) * DK + d0);
            float fs = (float)s;
            #pragma unroll
            for (int p = 0; p < 4; p++) {
                float sn, cs;
                sincosf(fs * invf[p], &sn, &cs);
                float e = acc[i][2 * p];
                float o = acc[i][2 * p + 1];
                dst[2 * p]     = e * cs - o * sn;
                dst[2 * p + 1] = o * cs + e * sn;
            }
        }
    }
}

// Kernel 3: d_out = g_attn @ w_o
__global__ __launch_bounds__(256, 2)
void oproj_gemm(const float* __restrict__ Bm, float* __restrict__ C) {
    __shared__ float As[2][BK][AS_STRIDE];
    __shared__ float Bs[2][BK][BN];

    const int tid = threadIdx.x;
    const int tx = tid & 15;
    const int ty = tid >> 4;
    const int m0 = blockIdx.y * BM;
    const int n0 = blockIdx.x * BN;

    float acc[8][8];
    #pragma unroll
    for (int i = 0; i < 8; i++)
        #pragma unroll
        for (int j = 0; j < 8; j++) acc[i][j] = 0.f;

    sgemm_mainloop<DM>(g_attn, Bm, m0, n0, acc, As, Bs);

    #pragma unroll
    for (int i = 0; i < 8; i++) {
        int m = m0 + ty * 8 + i;
        float* dst = C + (size_t)m * DM + n0 + tx * 8;
        *(float4*)(dst)     = *(float4*)(&acc[i][0]);
        *(float4*)(dst + 4) = *(float4*)(&acc[i][4]);
    }
}

// ---------------------------------------------------------------------------
// Kernel 2: sliding-window flash attention, 4 threads per query.
// grid (S/64, H, B), 256 threads. Thread t: query qs + (t>>2), dims
// [(t&3)*16, (t&3)*16+16). Score reduced across the 4-lane group via shfl.
// ---------------------------------------------------------------------------
__global__ __launch_bounds__(256)
void attn_kernel() {
    __shared__ float Ks[64][64];
    __shared__ float Vs[64][64];

    const int tid = threadIdx.x;
    const int qi  = tid >> 2;            // 0..63 local query
    const int sub = tid & 3;             // dim slice
    const int qs  = blockIdx.x * 64;
    const int h   = blockIdx.y;
    const int b   = blockIdx.z;
    const int i   = qs + qi;
    const unsigned gmask = 0xFu << ((tid & 31) & 28);  // 4-lane group mask

    const int   base = ((b * NH + h) * S_) * DK;
    const float* qp  = g_q + base + i * DK + sub * 16;
    const float* kp  = g_k + base;
    const float* vp  = g_v + base;

    float q0[16];
    #pragma unroll
    for (int r = 0; r < 4; r++) {
        float4 t = *(const float4*)(qp + 4 * r);
        q0[4*r+0] = t.x; q0[4*r+1] = t.y; q0[4*r+2] = t.z; q0[4*r+3] = t.w;
    }

    float m = -INFINITY, l = 0.f;
    float acc[16];
    #pragma unroll
    for (int d = 0; d < 16; d++) acc[d] = 0.f;

    const float scale = 0.125f;   // 1/sqrt(64)
    const int kc_start = (qs >= WIN) ? (qs - WIN) : 0;

    for (int kc = kc_start; kc < qs + 64; kc += 64) {
        // cooperative load: 2048 float4 across 256 threads
        #pragma unroll
        for (int it = 0; it < 4; it++) {
            int t = tid + it * 256;
            int row = t >> 4;
            int c4  = (t & 15) << 2;
            *(float4*)&Ks[row][c4] = *(const float4*)(kp + (kc + row) * DK + c4);
            *(float4*)&Vs[row][c4] = *(const float4*)(vp + (kc + row) * DK + c4);
        }
        __syncthreads();

        #pragma unroll 2
        for (int jj = 0; jj < 64; jj++) {
            int j = kc + jj;
            if (j <= i && j >= i - WIN) {   // uniform across the 4-lane group
                const float* kr = &Ks[jj][sub * 16];
                float s = 0.f;
                #pragma unroll
                for (int r = 0; r < 4; r++) {
                    float4 kk = *(const float4*)(kr + 4 * r);
                    s += q0[4*r+0]*kk.x + q0[4*r+1]*kk.y
                       + q0[4*r+2]*kk.z + q0[4*r+3]*kk.w;
                }
                s += __shfl_xor_sync(gmask, s, 1);
                s += __shfl_xor_sync(gmask, s, 2);
                s *= scale;

                const float* vr = &Vs[jj][sub * 16];
                if (s <= m) {
                    float p = __expf(s - m);
                    l += p;
                    #pragma unroll
                    for (int r = 0; r < 4; r++) {
                        float4 vv = *(const float4*)(vr + 4 * r);
                        acc[4*r+0] += p * vv.x;
                        acc[4*r+1] += p * vv.y;
                        acc[4*r+2] += p * vv.z;
                        acc[4*r+3] += p * vv.w;
                    }
                } else {
                    float corr = __expf(m - s);
                    m = s;
                    l = l * corr + 1.f;
                    #pragma unroll
                    for (int r = 0; r < 4; r++) {
                        float4 vv = *(const float4*)(vr + 4 * r);
                        acc[4*r+0] = acc[4*r+0] * corr + vv.x;
                        acc[4*r+1] = acc[4*r+1] * corr + vv.y;
                        acc[4*r+2] = acc[4*r+2] * corr + vv.z;
                        acc[4*r+3] = acc[4*r+3] * corr + vv.w;
                    }
                }
            }
        }
        __syncthreads();
    }

    const float inv_l = 1.f / l;
    float* op = g_attn + ((size_t)(b * S_ + i)) * DM + h * DK + sub * 16;
    #pragma unroll
    for (int r = 0; r < 4; r++) {
        float4 o;
        o.x = acc[4*r+0] * inv_l;
        o.y = acc[4*r+1] * inv_l;
        o.z = acc[4*r+2] * inv_l;
        o.w = acc[4*r+3] * inv_l;
        *(float4*)(op + 4 * r) = o;
    }
}

// ---------------------------------------------------------------------------
extern "C" void kernel_launch(void* const* d_in, const int* in_sizes, int n_in,
                              void* d_out, int out_size) {
    const float* x     = (const float*)d_in[0];   // [2,2048,1024]
    const float* w_qkv = (const float*)d_in[1];   // [1024,3072]
    const float* w_o   = (const float*)d_in[2];   // [1024,1024]
    float* out = (float*)d_out;                   // [2,2048,1024]

    // 1) QKV projection + RoPE
    {
        dim3 grid(3 * DM / BN, (B_ * S_) / BM);   // (24, 32)
        qkv_gemm_rope<<<grid, 256>>>(x, w_qkv);
    }
    // 2) Sliding-window attention
    {
        dim3 grid(S_ / 64, NH, B_);               // (32, 16, 2)
        attn_kernel<<<grid, 256>>>();
    }
    // 3) Output projection
    {
        dim3 grid(DM / BN, (B_ * S_) / BM);       // (8, 32)
        oproj_gemm<<<grid, 256>>>(w_o, out);
    }
}

// round 10
// speedup vs baseline: 2.0688x; 2.0688x over previous
#include <cuda_runtime.h>
#include <cuda_bf16.h>
#include <math.h>
#include <stdint.h>

#define B_  2
#define S_  2048
#define DM  1024
#define NH  16
#define DK  64
#define WIN 512
#define MTOT (B_*S_)   // 4096

// fp32 scratch
__device__ float g_q[B_*NH*S_*DK];      // [B,H,S,Dk]
__device__ float g_k[B_*NH*S_*DK];
__device__ float g_v[B_*NH*S_*DK];
__device__ float g_attn[B_*S_*DM];      // [B,S,D]

// bf16 hi/lo split scratch
__device__ __nv_bfloat16 g_xh[MTOT*DM],   g_xl[MTOT*DM];
__device__ __nv_bfloat16 g_wqh[DM*3*DM],  g_wql[DM*3*DM];
__device__ __nv_bfloat16 g_woh[DM*DM],    g_wol[DM*DM];
__device__ __nv_bfloat16 g_ah[MTOT*DM],   g_al[MTOT*DM];

// ---------------------------------------------------------------------------
// fp32 -> (hi, lo) bf16 split, 4 elements per thread
// ---------------------------------------------------------------------------
__global__ __launch_bounds__(256)
void split_kernel(const float* __restrict__ src,
                  __nv_bfloat16* __restrict__ hi,
                  __nv_bfloat16* __restrict__ lo, int n) {
    int i = (blockIdx.x * 256 + threadIdx.x) * 4;
    if (i >= n) return;
    float4 v = *(const float4*)(src + i);
    __nv_bfloat16 h0 = __float2bfloat16_rn(v.x);
    __nv_bfloat16 h1 = __float2bfloat16_rn(v.y);
    __nv_bfloat16 h2 = __float2bfloat16_rn(v.z);
    __nv_bfloat16 h3 = __float2bfloat16_rn(v.w);
    __nv_bfloat16 l0 = __float2bfloat16_rn(v.x - __bfloat162float(h0));
    __nv_bfloat16 l1 = __float2bfloat16_rn(v.y - __bfloat162float(h1));
    __nv_bfloat16 l2 = __float2bfloat16_rn(v.z - __bfloat162float(h2));
    __nv_bfloat16 l3 = __float2bfloat16_rn(v.w - __bfloat162float(h3));
    __nv_bfloat162* hp = (__nv_bfloat162*)(hi + i);
    __nv_bfloat162* lp = (__nv_bfloat162*)(lo + i);
    hp[0] = __nv_bfloat162(h0, h1);
    hp[1] = __nv_bfloat162(h2, h3);
    lp[0] = __nv_bfloat162(l0, l1);
    lp[1] = __nv_bfloat162(l2, l3);
}

// ---------------------------------------------------------------------------
// Tensor-core GEMM: C = Ah*Bh + Ah*Bl + Al*Bh  (fp32 accum)
// Block tile 128x64, BK=16 (bf16), 256 threads = 8 warps, warp tile 32x32.
// A smem [BM][BK] row-major (ldmatrix), B smem [BK][BN] (ldmatrix.trans).
// ---------------------------------------------------------------------------
#define BM 128
#define BN 64
#define BKT 16
#define APAD 8    // A row stride 24 bf16 = 48B  -> ldmatrix conflict-free
#define BPAD 8    // B row stride 72 bf16 = 144B -> ldmatrix conflict-free

__device__ __forceinline__ unsigned smem_u32(const void* p) {
    return (unsigned)__cvta_generic_to_shared(p);
}
#define CP_ASYNC16(dst_u32, src_ptr) \
    asm volatile("cp.async.cg.shared.global [%0], [%1], 16;\n" :: "r"(dst_u32), "l"(src_ptr))
#define CP_COMMIT() asm volatile("cp.async.commit_group;\n" ::: "memory")

__device__ __forceinline__ void ldsm4(uint32_t a, uint32_t* r) {
    asm volatile("ldmatrix.sync.aligned.m8n8.x4.shared.b16 {%0,%1,%2,%3}, [%4];\n"
        : "=r"(r[0]), "=r"(r[1]), "=r"(r[2]), "=r"(r[3]) : "r"(a));
}
__device__ __forceinline__ void ldsm4t(uint32_t a, uint32_t* r) {
    asm volatile("ldmatrix.sync.aligned.m8n8.x4.trans.shared.b16 {%0,%1,%2,%3}, [%4];\n"
        : "=r"(r[0]), "=r"(r[1]), "=r"(r[2]), "=r"(r[3]) : "r"(a));
}
__device__ __forceinline__ void mma16816(float* c, const uint32_t* a, uint32_t b0, uint32_t b1) {
    asm volatile("mma.sync.aligned.m16n8k16.row.col.f32.bf16.bf16.f32 "
        "{%0,%1,%2,%3}, {%4,%5,%6,%7}, {%8,%9}, {%0,%1,%2,%3};\n"
        : "+f"(c[0]), "+f"(c[1]), "+f"(c[2]), "+f"(c[3])
        : "r"(a[0]), "r"(a[1]), "r"(a[2]), "r"(a[3]), "r"(b0), "r"(b1));
}

// acc[mi][ni][4]: mi in {0,1} (m16 tiles), ni in {0..3} (n8 tiles)
__device__ __forceinline__ void mma_mainloop(
    const __nv_bfloat16* __restrict__ Ah, const __nv_bfloat16* __restrict__ Al,
    const __nv_bfloat16* __restrict__ Bh, const __nv_bfloat16* __restrict__ Bl,
    int m0, int n0, int N,
    float acc[2][4][4],
    __nv_bfloat16 (*As)[2][BM][BKT + APAD],
    __nv_bfloat16 (*Bs)[2][BKT][BN + BPAD])
{
    const int K = DM;
    const int tid  = threadIdx.x;
    const int lane = tid & 31;
    const int wid  = tid >> 5;
    const int wx   = wid & 1;    // N warp: 0..1 (32 cols each)
    const int wy   = wid >> 1;   // M warp: 0..3 (32 rows each)

    // global->smem load coords
    const int a_row = tid >> 1;              // 0..127
    const int a_col = (tid & 1) * 8;         // 0 or 8 (bf16 elems)
    const int b_sp  = tid >> 7;              // split handled by this half
    const int b_r   = (tid >> 3) & 15;       // 0..15
    const int b_c   = (tid & 7) * 8;         // 0..56

    // ldmatrix lane addressing
    const int a_lrow = lane & 15;
    const int a_lcol = (lane >> 4) * 8;
    const int b_krow = ((lane >> 3) & 1) * 8 + (lane & 7);
    const int b_noff = ((lane >> 4) & 1) * 8;

    auto load_tile = [&](int buf, int kt) {
        CP_ASYNC16(smem_u32(&As[buf][0][a_row][a_col]),
                   Ah + (size_t)(m0 + a_row) * K + kt + a_col);
        CP_ASYNC16(smem_u32(&As[buf][1][a_row][a_col]),
                   Al + (size_t)(m0 + a_row) * K + kt + a_col);
        const __nv_bfloat16* Bp = b_sp ? Bl : Bh;
        CP_ASYNC16(smem_u32(&Bs[buf][b_sp][b_r][b_c]),
                   Bp + (size_t)(kt + b_r) * N + n0 + b_c);
    };

    load_tile(0, 0);
    CP_COMMIT();

    int buf = 0;
    for (int kt = 0; kt < K; kt += BKT, buf ^= 1) {
        const bool has_next = (kt + BKT) < K;
        if (has_next) {
            load_tile(buf ^ 1, kt + BKT);
            CP_COMMIT();
            asm volatile("cp.async.wait_group 1;\n" ::: "memory");
        } else {
            asm volatile("cp.async.wait_group 0;\n" ::: "memory");
        }
        __syncthreads();

        // fragments
        uint32_t af[2][2][4];   // [split][mi][4]
        #pragma unroll
        for (int sp = 0; sp < 2; sp++)
            #pragma unroll
            for (int mi = 0; mi < 2; mi++)
                ldsm4(smem_u32(&As[buf][sp][wy * 32 + mi * 16 + a_lrow][a_lcol]),
                      af[sp][mi]);

        uint32_t bfr[2][2][4];  // [split][nj][4]: (r0,r1)=n-tile 2*nj, (r2,r3)=2*nj+1
        #pragma unroll
        for (int sp = 0; sp < 2; sp++)
            #pragma unroll
            for (int nj = 0; nj < 2; nj++)
                ldsm4t(smem_u32(&Bs[buf][sp][b_krow][wx * 32 + nj * 16 + b_noff]),
                       bfr[sp][nj]);

        #pragma unroll
        for (int mi = 0; mi < 2; mi++)
            #pragma unroll
            for (int ni = 0; ni < 4; ni++) {
                const int nj = ni >> 1, sel = (ni & 1) * 2;
                mma16816(acc[mi][ni], af[0][mi], bfr[0][nj][sel], bfr[0][nj][sel + 1]); // hi*hi
                mma16816(acc[mi][ni], af[0][mi], bfr[1][nj][sel], bfr[1][nj][sel + 1]); // hi*lo
                mma16816(acc[mi][ni], af[1][mi], bfr[0][nj][sel], bfr[0][nj][sel + 1]); // lo*hi
            }
        __syncthreads();
    }
}

// Kernel 1: qkv = x @ w_qkv with fused RoPE epilogue into g_q/g_k/g_v
__global__ __launch_bounds__(256)
void qkv_mma_rope() {
    __shared__ __align__(16) __nv_bfloat16 As[2][2][BM][BKT + APAD];
    __shared__ __align__(16) __nv_bfloat16 Bs[2][2][BKT][BN + BPAD];

    const int m0 = blockIdx.y * BM;
    const int n0 = blockIdx.x * BN;

    float acc[2][4][4];
    #pragma unroll
    for (int mi = 0; mi < 2; mi++)
        #pragma unroll
        for (int ni = 0; ni < 4; ni++)
            #pragma unroll
            for (int r = 0; r < 4; r++) acc[mi][ni][r] = 0.f;

    mma_mainloop(g_xh, g_xl, g_wqh, g_wql, m0, n0, 3 * DM, acc, As, Bs);

    const int lane = threadIdx.x & 31;
    const int wid  = threadIdx.x >> 5;
    const int wx   = wid & 1;
    const int wy   = wid >> 1;
    const int g    = lane >> 2;
    const int tig  = lane & 3;

    const int which = n0 >> 10;            // 0=q 1=k 2=v (n0 multiple of 64)
    const int h     = (n0 & 1023) >> 6;    // constant per block
    float* base = (which == 0) ? g_q : (which == 1) ? g_k : g_v;

    // precompute inv_freq per ni (d depends only on wx, ni, tig)
    float invf[4];
    #pragma unroll
    for (int ni = 0; ni < 4; ni++) {
        int d = wx * 32 + ni * 8 + tig * 2;
        invf[ni] = powf(10000.0f, -(float)(d >> 1) / 32.0f);
    }

    #pragma unroll
    for (int mi = 0; mi < 2; mi++) {
        #pragma unroll
        for (int half = 0; half < 2; half++) {
            int m = m0 + wy * 32 + mi * 16 + g + half * 8;
            int b = m >> 11, s = m & 2047;
            float fs = (float)s;
            float* rowp = base + ((size_t)(b * NH + h) * S_ + s) * DK;
            #pragma unroll
            for (int ni = 0; ni < 4; ni++) {
                int d = wx * 32 + ni * 8 + tig * 2;
                float e = acc[mi][ni][half * 2 + 0];
                float o = acc[mi][ni][half * 2 + 1];
                float2 out;
                if (which == 2) {
                    out.x = e; out.y = o;
                } else {
                    float sn, cs;
                    sincosf(fs * invf[ni], &sn, &cs);
                    out.x = e * cs - o * sn;
                    out.y = o * cs + e * sn;
                }
                *(float2*)(rowp + d) = out;
            }
        }
    }
}

// Kernel 3: d_out = g_attn @ w_o
__global__ __launch_bounds__(256)
void oproj_mma(float* __restrict__ C) {
    __shared__ __align__(16) __nv_bfloat16 As[2][2][BM][BKT + APAD];
    __shared__ __align__(16) __nv_bfloat16 Bs[2][2][BKT][BN + BPAD];

    const int m0 = blockIdx.y * BM;
    const int n0 = blockIdx.x * BN;

    float acc[2][4][4];
    #pragma unroll
    for (int mi = 0; mi < 2; mi++)
        #pragma unroll
        for (int ni = 0; ni < 4; ni++)
            #pragma unroll
            for (int r = 0; r < 4; r++) acc[mi][ni][r] = 0.f;

    mma_mainloop(g_ah, g_al, g_woh, g_wol, m0, n0, DM, acc, As, Bs);

    const int lane = threadIdx.x & 31;
    const int wid  = threadIdx.x >> 5;
    const int wx   = wid & 1;
    const int wy   = wid >> 1;
    const int g    = lane >> 2;
    const int tig  = lane & 3;

    #pragma unroll
    for (int mi = 0; mi < 2; mi++) {
        #pragma unroll
        for (int half = 0; half < 2; half++) {
            int m = m0 + wy * 32 + mi * 16 + g + half * 8;
            #pragma unroll
            for (int ni = 0; ni < 4; ni++) {
                int d = wx * 32 + ni * 8 + tig * 2;
                float2 out;
                out.x = acc[mi][ni][half * 2 + 0];
                out.y = acc[mi][ni][half * 2 + 1];
                *(float2*)(C + (size_t)m * DM + n0 + d) = out;
            }
        }
    }
}

// ---------------------------------------------------------------------------
// Kernel 2: sliding-window flash attention (round-1 known-good version).
// grid (S/64, H, B), 64 threads; thread t owns query i = qs + t.
// ---------------------------------------------------------------------------
__global__ __launch_bounds__(64)
void attn_kernel() {
    __shared__ float Ks[64][64];
    __shared__ float Vs[64][64];

    const int tid = threadIdx.x;
    const int qs  = blockIdx.x * 64;
    const int h   = blockIdx.y;
    const int b   = blockIdx.z;
    const int i   = qs + tid;

    const int   base = ((b * NH + h) * S_) * DK;
    const float* qp  = g_q + base + i * DK;
    const float* kp  = g_k + base;
    const float* vp  = g_v + base;

    float qreg[64];
    #pragma unroll
    for (int d4 = 0; d4 < 16; d4++) {
        float4 t = *(const float4*)(qp + d4 * 4);
        qreg[d4 * 4 + 0] = t.x; qreg[d4 * 4 + 1] = t.y;
        qreg[d4 * 4 + 2] = t.z; qreg[d4 * 4 + 3] = t.w;
    }

    float m = -INFINITY, l = 0.f;
    float acc[64];
    #pragma unroll
    for (int d = 0; d < 64; d++) acc[d] = 0.f;

    const float scale = 0.125f;   // 1/sqrt(64)
    const int kc_start = (qs >= WIN) ? (qs - WIN) : 0;

    for (int kc = kc_start; kc < qs + 64; kc += 64) {
        for (int t = tid; t < 1024; t += 64) {
            int row = t >> 4;
            int c4  = (t & 15) << 2;
            *(float4*)&Ks[row][c4] = *(const float4*)(kp + (kc + row) * DK + c4);
            *(float4*)&Vs[row][c4] = *(const float4*)(vp + (kc + row) * DK + c4);
        }
        __syncthreads();

        #pragma unroll 4
        for (int jj = 0; jj < 64; jj++) {
            int j = kc + jj;
            if (j <= i && j >= i - WIN) {
                float s = 0.f;
                #pragma unroll
                for (int d4 = 0; d4 < 16; d4++) {
                    float4 kk4 = *(float4*)&Ks[jj][d4 * 4];
                    s += qreg[d4*4+0]*kk4.x + qreg[d4*4+1]*kk4.y
                       + qreg[d4*4+2]*kk4.z + qreg[d4*4+3]*kk4.w;
                }
                s *= scale;
                if (s <= m) {
                    float p = __expf(s - m);
                    l += p;
                    #pragma unroll
                    for (int d4 = 0; d4 < 16; d4++) {
                        float4 vv = *(float4*)&Vs[jj][d4 * 4];
                        acc[d4*4+0] += p * vv.x;
                        acc[d4*4+1] += p * vv.y;
                        acc[d4*4+2] += p * vv.z;
                        acc[d4*4+3] += p * vv.w;
                    }
                } else {
                    float corr = __expf(m - s);
                    m = s;
                    l = l * corr + 1.f;
                    #pragma unroll
                    for (int d4 = 0; d4 < 16; d4++) {
                        float4 vv = *(float4*)&Vs[jj][d4 * 4];
                        acc[d4*4+0] = acc[d4*4+0] * corr + vv.x;
                        acc[d4*4+1] = acc[d4*4+1] * corr + vv.y;
                        acc[d4*4+2] = acc[d4*4+2] * corr + vv.z;
                        acc[d4*4+3] = acc[d4*4+3] * corr + vv.w;
                    }
                }
            }
        }
        __syncthreads();
    }

    const float inv_l = 1.f / l;
    float* op = g_attn + ((size_t)(b * S_ + i)) * DM + h * DK;
    #pragma unroll
    for (int d4 = 0; d4 < 16; d4++) {
        float4 o;
        o.x = acc[d4*4+0] * inv_l;
        o.y = acc[d4*4+1] * inv_l;
        o.z = acc[d4*4+2] * inv_l;
        o.w = acc[d4*4+3] * inv_l;
        *(float4*)(op + d4 * 4) = o;
    }
}

// ---------------------------------------------------------------------------
extern "C" void kernel_launch(void* const* d_in, const int* in_sizes, int n_in,
                              void* d_out, int out_size) {
    const float* x     = (const float*)d_in[0];   // [2,2048,1024]
    const float* w_qkv = (const float*)d_in[1];   // [1024,3072]
    const float* w_o   = (const float*)d_in[2];   // [1024,1024]
    float* out = (float*)d_out;                   // [2,2048,1024]

    __nv_bfloat16 *xh, *xl, *wqh, *wql, *woh, *wol, *ah, *al;
    cudaGetSymbolAddress((void**)&xh,  g_xh);
    cudaGetSymbolAddress((void**)&xl,  g_xl);
    cudaGetSymbolAddress((void**)&wqh, g_wqh);
    cudaGetSymbolAddress((void**)&wql, g_wql);
    cudaGetSymbolAddress((void**)&woh, g_woh);
    cudaGetSymbolAddress((void**)&wol, g_wol);
    cudaGetSymbolAddress((void**)&ah,  g_ah);
    cudaGetSymbolAddress((void**)&al,  g_al);
    float* attnp;
    cudaGetSymbolAddress((void**)&attnp, g_attn);

    // 0) hi/lo bf16 splits of x and weights
    split_kernel<<<MTOT * DM / 1024, 256>>>(x, xh, xl, MTOT * DM);
    split_kernel<<<DM * 3 * DM / 1024, 256>>>(w_qkv, wqh, wql, DM * 3 * DM);
    split_kernel<<<DM * DM / 1024, 256>>>(w_o, woh, wol, DM * DM);

    // 1) QKV projection (tensor core) + RoPE
    {
        dim3 grid(3 * DM / BN, MTOT / BM);   // (48, 32)
        qkv_mma_rope<<<grid, 256>>>();
    }
    // 2) Sliding-window attention (fp32)
    {
        dim3 grid(S_ / 64, NH, B_);          // (32, 16, 2)
        attn_kernel<<<grid, 64>>>();
    }
    // 2b) split attention output
    split_kernel<<<MTOT * DM / 1024, 256>>>(attnp, ah, al, MTOT * DM);

    // 3) Output projection (tensor core)
    {
        dim3 grid(DM / BN, MTOT / BM);       // (16, 32)
        oproj_mma<<<grid, 256>>>(out);
    }
}

// round 11
// speedup vs baseline: 3.7553x; 1.8152x over previous
#include <cuda_runtime.h>
#include <cuda_bf16.h>
#include <math.h>
#include <stdint.h>

#define B_  2
#define S_  2048
#define DM  1024
#define NH  16
#define DK  64
#define WIN 512
#define MTOT (B_*S_)   // 4096

// bf16 hi/lo split scratch (allocation-free rule: __device__ globals)
__device__ __nv_bfloat16 g_xh[MTOT*DM],   g_xl[MTOT*DM];
__device__ __nv_bfloat16 g_wqh[DM*3*DM],  g_wql[DM*3*DM];
__device__ __nv_bfloat16 g_woh[DM*DM],    g_wol[DM*DM];
__device__ __nv_bfloat16 g_ah[MTOT*DM],   g_al[MTOT*DM];
// q/k/v in [B,H,S,DK], bf16 hi/lo (q pre-scaled by 1/8, rope applied)
__device__ __nv_bfloat16 g_qh[B_*NH*S_*DK], g_ql[B_*NH*S_*DK];
__device__ __nv_bfloat16 g_kh[B_*NH*S_*DK], g_kl[B_*NH*S_*DK];
__device__ __nv_bfloat16 g_vh[B_*NH*S_*DK], g_vl[B_*NH*S_*DK];

// ---------------------------------------------------------------------------
// helpers
// ---------------------------------------------------------------------------
__device__ __forceinline__ unsigned smem_u32(const void* p) {
    return (unsigned)__cvta_generic_to_shared(p);
}
#define CP_ASYNC16(dst_u32, src_ptr) \
    asm volatile("cp.async.cg.shared.global [%0], [%1], 16;\n" :: "r"(dst_u32), "l"(src_ptr))
#define CP_COMMIT() asm volatile("cp.async.commit_group;\n" ::: "memory")

__device__ __forceinline__ void ldsm4(uint32_t a, uint32_t* r) {
    asm volatile("ldmatrix.sync.aligned.m8n8.x4.shared.b16 {%0,%1,%2,%3}, [%4];\n"
        : "=r"(r[0]), "=r"(r[1]), "=r"(r[2]), "=r"(r[3]) : "r"(a));
}
__device__ __forceinline__ void ldsm4t(uint32_t a, uint32_t* r) {
    asm volatile("ldmatrix.sync.aligned.m8n8.x4.trans.shared.b16 {%0,%1,%2,%3}, [%4];\n"
        : "=r"(r[0]), "=r"(r[1]), "=r"(r[2]), "=r"(r[3]) : "r"(a));
}
__device__ __forceinline__ void mma16816(float* c, const uint32_t* a, uint32_t b0, uint32_t b1) {
    asm volatile("mma.sync.aligned.m16n8k16.row.col.f32.bf16.bf16.f32 "
        "{%0,%1,%2,%3}, {%4,%5,%6,%7}, {%8,%9}, {%0,%1,%2,%3};\n"
        : "+f"(c[0]), "+f"(c[1]), "+f"(c[2]), "+f"(c[3])
        : "r"(a[0]), "r"(a[1]), "r"(a[2]), "r"(a[3]), "r"(b0), "r"(b1));
}
__device__ __forceinline__ uint32_t packbf(__nv_bfloat16 a, __nv_bfloat16 b) {
    __nv_bfloat162 t(a, b);
    return *(uint32_t*)&t;
}
__device__ __forceinline__ void store_split(__nv_bfloat16* hi, __nv_bfloat16* lo,
                                            size_t idx, float x, float y) {
    __nv_bfloat16 hx = __float2bfloat16_rn(x), hy = __float2bfloat16_rn(y);
    __nv_bfloat16 lx = __float2bfloat16_rn(x - __bfloat162float(hx));
    __nv_bfloat16 ly = __float2bfloat16_rn(y - __bfloat162float(hy));
    *(__nv_bfloat162*)(hi + idx) = __nv_bfloat162(hx, hy);
    *(__nv_bfloat162*)(lo + idx) = __nv_bfloat162(lx, ly);
}

// ---------------------------------------------------------------------------
// fp32 -> (hi, lo) bf16 split, 4 elements per thread
// ---------------------------------------------------------------------------
__global__ __launch_bounds__(256)
void split_kernel(const float* __restrict__ src,
                  __nv_bfloat16* __restrict__ hi,
                  __nv_bfloat16* __restrict__ lo, int n) {
    int i = (blockIdx.x * 256 + threadIdx.x) * 4;
    if (i >= n) return;
    float4 v = *(const float4*)(src + i);
    store_split(hi, lo, i,     v.x, v.y);
    store_split(hi, lo, i + 2, v.z, v.w);
}

// ---------------------------------------------------------------------------
// Tensor-core GEMM: C = Ah*Bh + Ah*Bl + Al*Bh  (fp32 accum)
// Block tile 128x64, BK=16, 256 threads = 8 warps, warp tile 32x32.
// ---------------------------------------------------------------------------
#define BM 128
#define BN 64
#define BKT 16
#define APAD 8
#define BPAD 8

__device__ __forceinline__ void mma_mainloop(
    const __nv_bfloat16* __restrict__ Ah, const __nv_bfloat16* __restrict__ Al,
    const __nv_bfloat16* __restrict__ Bh, const __nv_bfloat16* __restrict__ Bl,
    int m0, int n0, int N,
    float acc[2][4][4],
    __nv_bfloat16 (*As)[2][BM][BKT + APAD],
    __nv_bfloat16 (*Bs)[2][BKT][BN + BPAD])
{
    const int K = DM;
    const int tid  = threadIdx.x;
    const int lane = tid & 31;
    const int wid  = tid >> 5;
    const int wx   = wid & 1;
    const int wy   = wid >> 1;

    const int a_row = tid >> 1;
    const int a_col = (tid & 1) * 8;
    const int b_sp  = tid >> 7;
    const int b_r   = (tid >> 3) & 15;
    const int b_c   = (tid & 7) * 8;

    const int a_lrow = lane & 15;
    const int a_lcol = (lane >> 4) * 8;
    const int b_krow = ((lane >> 3) & 1) * 8 + (lane & 7);
    const int b_noff = ((lane >> 4) & 1) * 8;

    auto load_tile = [&](int buf, int kt) {
        CP_ASYNC16(smem_u32(&As[buf][0][a_row][a_col]),
                   Ah + (size_t)(m0 + a_row) * K + kt + a_col);
        CP_ASYNC16(smem_u32(&As[buf][1][a_row][a_col]),
                   Al + (size_t)(m0 + a_row) * K + kt + a_col);
        const __nv_bfloat16* Bp = b_sp ? Bl : Bh;
        CP_ASYNC16(smem_u32(&Bs[buf][b_sp][b_r][b_c]),
                   Bp + (size_t)(kt + b_r) * N + n0 + b_c);
    };

    load_tile(0, 0);
    CP_COMMIT();

    int buf = 0;
    for (int kt = 0; kt < K; kt += BKT, buf ^= 1) {
        const bool has_next = (kt + BKT) < K;
        if (has_next) {
            load_tile(buf ^ 1, kt + BKT);
            CP_COMMIT();
            asm volatile("cp.async.wait_group 1;\n" ::: "memory");
        } else {
            asm volatile("cp.async.wait_group 0;\n" ::: "memory");
        }
        __syncthreads();

        uint32_t af[2][2][4];
        #pragma unroll
        for (int sp = 0; sp < 2; sp++)
            #pragma unroll
            for (int mi = 0; mi < 2; mi++)
                ldsm4(smem_u32(&As[buf][sp][wy * 32 + mi * 16 + a_lrow][a_lcol]),
                      af[sp][mi]);

        uint32_t bfr[2][2][4];
        #pragma unroll
        for (int sp = 0; sp < 2; sp++)
            #pragma unroll
            for (int nj = 0; nj < 2; nj++)
                ldsm4t(smem_u32(&Bs[buf][sp][b_krow][wx * 32 + nj * 16 + b_noff]),
                       bfr[sp][nj]);

        #pragma unroll
        for (int mi = 0; mi < 2; mi++)
            #pragma unroll
            for (int ni = 0; ni < 4; ni++) {
                const int nj = ni >> 1, sel = (ni & 1) * 2;
                mma16816(acc[mi][ni], af[0][mi], bfr[0][nj][sel], bfr[0][nj][sel + 1]);
                mma16816(acc[mi][ni], af[0][mi], bfr[1][nj][sel], bfr[1][nj][sel + 1]);
                mma16816(acc[mi][ni], af[1][mi], bfr[0][nj][sel], bfr[0][nj][sel + 1]);
            }
        __syncthreads();
    }
}

// Kernel 1: qkv = x @ w_qkv; epilogue applies RoPE (+1/8 scale on q) and
// writes bf16 hi/lo q/k/v directly.
__global__ __launch_bounds__(256)
void qkv_mma_rope() {
    __shared__ __align__(16) __nv_bfloat16 As[2][2][BM][BKT + APAD];
    __shared__ __align__(16) __nv_bfloat16 Bs[2][2][BKT][BN + BPAD];

    const int m0 = blockIdx.y * BM;
    const int n0 = blockIdx.x * BN;

    float acc[2][4][4];
    #pragma unroll
    for (int mi = 0; mi < 2; mi++)
        #pragma unroll
        for (int ni = 0; ni < 4; ni++)
            #pragma unroll
            for (int r = 0; r < 4; r++) acc[mi][ni][r] = 0.f;

    mma_mainloop(g_xh, g_xl, g_wqh, g_wql, m0, n0, 3 * DM, acc, As, Bs);

    const int lane = threadIdx.x & 31;
    const int wid  = threadIdx.x >> 5;
    const int wx   = wid & 1;
    const int wy   = wid >> 1;
    const int g    = lane >> 2;
    const int tig  = lane & 3;

    const int which = n0 >> 10;            // 0=q 1=k 2=v
    const int h     = (n0 & 1023) >> 6;
    __nv_bfloat16* hb = (which == 0) ? g_qh : (which == 1) ? g_kh : g_vh;
    __nv_bfloat16* lb = (which == 0) ? g_ql : (which == 1) ? g_kl : g_vl;
    const float qscale = (which == 0) ? 0.125f : 1.0f;

    float invf[4];
    #pragma unroll
    for (int ni = 0; ni < 4; ni++) {
        int d = wx * 32 + ni * 8 + tig * 2;
        invf[ni] = powf(10000.0f, -(float)(d >> 1) / 32.0f);
    }

    #pragma unroll
    for (int mi = 0; mi < 2; mi++) {
        #pragma unroll
        for (int half = 0; half < 2; half++) {
            int m = m0 + wy * 32 + mi * 16 + g + half * 8;
            int bb = m >> 11, s = m & 2047;
            float fs = (float)s;
            size_t rowoff = ((size_t)(bb * NH + h) * S_ + s) * DK;
            #pragma unroll
            for (int ni = 0; ni < 4; ni++) {
                int d = wx * 32 + ni * 8 + tig * 2;
                float e = acc[mi][ni][half * 2 + 0];
                float o = acc[mi][ni][half * 2 + 1];
                float ox, oy;
                if (which == 2) {
                    ox = e; oy = o;
                } else {
                    float sn, cs;
                    sincosf(fs * invf[ni], &sn, &cs);
                    ox = (e * cs - o * sn) * qscale;
                    oy = (o * cs + e * sn) * qscale;
                }
                store_split(hb, lb, rowoff + d, ox, oy);
            }
        }
    }
}

// Kernel 3: d_out = attn_out @ w_o
__global__ __launch_bounds__(256)
void oproj_mma(float* __restrict__ C) {
    __shared__ __align__(16) __nv_bfloat16 As[2][2][BM][BKT + APAD];
    __shared__ __align__(16) __nv_bfloat16 Bs[2][2][BKT][BN + BPAD];

    const int m0 = blockIdx.y * BM;
    const int n0 = blockIdx.x * BN;

    float acc[2][4][4];
    #pragma unroll
    for (int mi = 0; mi < 2; mi++)
        #pragma unroll
        for (int ni = 0; ni < 4; ni++)
            #pragma unroll
            for (int r = 0; r < 4; r++) acc[mi][ni][r] = 0.f;

    mma_mainloop(g_ah, g_al, g_woh, g_wol, m0, n0, DM, acc, As, Bs);

    const int lane = threadIdx.x & 31;
    const int wid  = threadIdx.x >> 5;
    const int wx   = wid & 1;
    const int wy   = wid >> 1;
    const int g    = lane >> 2;
    const int tig  = lane & 3;

    #pragma unroll
    for (int mi = 0; mi < 2; mi++) {
        #pragma unroll
        for (int half = 0; half < 2; half++) {
            int m = m0 + wy * 32 + mi * 16 + g + half * 8;
            #pragma unroll
            for (int ni = 0; ni < 4; ni++) {
                int d = wx * 32 + ni * 8 + tig * 2;
                float2 out;
                out.x = acc[mi][ni][half * 2 + 0];
                out.y = acc[mi][ni][half * 2 + 1];
                *(float2*)(C + (size_t)m * DM + n0 + d) = out;
            }
        }
    }
}

// ---------------------------------------------------------------------------
// Kernel 2: sliding-window flash attention on tensor cores.
// grid (S/64, H, B), 128 threads = 4 warps; warp w owns queries
// [qs + 16w, qs + 16w + 16). Key tiles of 64. hi/lo-split bf16 MMAs.
// ---------------------------------------------------------------------------
#define ATP 8   // smem pad (row stride 72 bf16 = 144B, ldsm conflict-free)

__global__ __launch_bounds__(128)
void attn_mma() {
    __shared__ __align__(16) __nv_bfloat16 Ks[2][64][64 + ATP];
    __shared__ __align__(16) __nv_bfloat16 Vs[2][64][64 + ATP];

    const int tid  = threadIdx.x;
    const int lane = tid & 31;
    const int w    = tid >> 5;          // 0..3
    const int g    = lane >> 2;
    const int tig  = lane & 3;
    const int qs   = blockIdx.x * 64;
    const int h    = blockIdx.y;
    const int bb   = blockIdx.z;

    const size_t base = ((size_t)(bb * NH + h)) * S_ * DK;

    // ---- stage Q tile (hi/lo) through Ks, load A-fragments ----
    #pragma unroll
    for (int it = 0; it < 8; it++) {
        int c   = tid + it * 128;
        int sp  = c >> 9;
        int rem = c & 511;
        int row = rem >> 3;
        int col = (rem & 7) * 8;
        const __nv_bfloat16* src = (sp ? g_ql : g_qh) + base + (size_t)(qs + row) * DK + col;
        CP_ASYNC16(smem_u32(&Ks[sp][row][col]), src);
    }
    CP_COMMIT();
    asm volatile("cp.async.wait_group 0;\n" ::: "memory");
    __syncthreads();

    const int a_lrow = lane & 15;
    const int a_lcol = (lane >> 4) * 8;
    uint32_t qa[2][4][4];
    #pragma unroll
    for (int sp = 0; sp < 2; sp++)
        #pragma unroll
        for (int kt = 0; kt < 4; kt++)
            ldsm4(smem_u32(&Ks[sp][w * 16 + a_lrow][kt * 16 + a_lcol]), qa[sp][kt]);
    __syncthreads();

    // K B-frag addressing: tile t = lane>>3: n-block (t&1), k-block (t>>1)
    const int kb_t    = lane >> 3;
    const int kb_nrow = (kb_t & 1) * 8 + (lane & 7);
    const int kb_kcol = (kb_t >> 1) * 8;
    // V B-frag addressing (ldsm trans, same as GEMM B)
    const int vb_krow = ((lane >> 3) & 1) * 8 + (lane & 7);
    const int vb_noff = ((lane >> 4) & 1) * 8;

    float m0 = -1e30f, m1 = -1e30f;
    float l0 = 0.f, l1 = 0.f;           // per-lane partials
    float acc_o[8][4];
    #pragma unroll
    for (int nt = 0; nt < 8; nt++)
        #pragma unroll
        for (int r = 0; r < 4; r++) acc_o[nt][r] = 0.f;

    const int i0 = qs + w * 16 + g;     // row of c0/c1; c2/c3 at i0+8
    const int kc_start = (qs >= WIN) ? (qs - WIN) : 0;

    for (int kc = kc_start; kc <= qs; kc += 64) {
        // ---- load K,V hi/lo tiles ----
        #pragma unroll
        for (int it = 0; it < 16; it++) {
            int c   = tid + it * 128;
            int arr = c >> 9;               // 0..3
            int rem = c & 511;
            int row = rem >> 3;
            int col = (rem & 7) * 8;
            const __nv_bfloat16* src =
                (arr == 0 ? g_kh : arr == 1 ? g_kl : arr == 2 ? g_vh : g_vl)
                + base + (size_t)(kc + row) * DK + col;
            unsigned dst = (arr < 2) ? smem_u32(&Ks[arr][row][col])
                                     : smem_u32(&Vs[arr - 2][row][col]);
            CP_ASYNC16(dst, src);
        }
        CP_COMMIT();
        asm volatile("cp.async.wait_group 0;\n" ::: "memory");
        __syncthreads();

        // ---- scores: S = Q K^T (split, fp32 accum) ----
        float s[8][4];
        #pragma unroll
        for (int nt = 0; nt < 8; nt++)
            #pragma unroll
            for (int r = 0; r < 4; r++) s[nt][r] = 0.f;

        #pragma unroll
        for (int kt = 0; kt < 4; kt++) {
            #pragma unroll
            for (int nc = 0; nc < 4; nc++) {
                uint32_t kh[4], kl[4];
                ldsm4(smem_u32(&Ks[0][nc * 16 + kb_nrow][kt * 16 + kb_kcol]), kh);
                ldsm4(smem_u32(&Ks[1][nc * 16 + kb_nrow][kt * 16 + kb_kcol]), kl);
                // n-tile 2nc: (r0,r2); n-tile 2nc+1: (r1,r3)
                mma16816(s[2 * nc],     qa[0][kt], kh[0], kh[2]);
                mma16816(s[2 * nc],     qa[0][kt], kl[0], kl[2]);
                mma16816(s[2 * nc],     qa[1][kt], kh[0], kh[2]);
                mma16816(s[2 * nc + 1], qa[0][kt], kh[1], kh[3]);
                mma16816(s[2 * nc + 1], qa[0][kt], kl[1], kl[3]);
                mma16816(s[2 * nc + 1], qa[1][kt], kh[1], kh[3]);
            }
        }

        // ---- mask (only boundary tiles need it) ----
        if (kc == qs || kc + WIN == qs) {
            #pragma unroll
            for (int nt = 0; nt < 8; nt++) {
                int jb = kc + nt * 8 + tig * 2;
                #pragma unroll
                for (int r = 0; r < 4; r++) {
                    int j = jb + (r & 1);
                    int i = i0 + ((r >= 2) ? 8 : 0);
                    if (j > i || j < i - WIN) s[nt][r] = -1e30f;
                }
            }
        }

        // ---- online softmax ----
        float t0 = -1e30f, t1 = -1e30f;
        #pragma unroll
        for (int nt = 0; nt < 8; nt++) {
            t0 = fmaxf(t0, fmaxf(s[nt][0], s[nt][1]));
            t1 = fmaxf(t1, fmaxf(s[nt][2], s[nt][3]));
        }
        t0 = fmaxf(t0, __shfl_xor_sync(0xffffffffu, t0, 1));
        t0 = fmaxf(t0, __shfl_xor_sync(0xffffffffu, t0, 2));
        t1 = fmaxf(t1, __shfl_xor_sync(0xffffffffu, t1, 1));
        t1 = fmaxf(t1, __shfl_xor_sync(0xffffffffu, t1, 2));

        float mn0 = fmaxf(m0, t0), mn1 = fmaxf(m1, t1);
        float corr0 = __expf(m0 - mn0), corr1 = __expf(m1 - mn1);
        m0 = mn0; m1 = mn1;

        uint32_t ph[4][4], pl[4][4];
        float suml0 = 0.f, suml1 = 0.f;
        #pragma unroll
        for (int kt = 0; kt < 4; kt++) {
            #pragma unroll
            for (int half = 0; half < 2; half++) {
                int nt = 2 * kt + half;
                float p0 = __expf(s[nt][0] - m0);
                float p1 = __expf(s[nt][1] - m0);
                float p2 = __expf(s[nt][2] - m1);
                float p3 = __expf(s[nt][3] - m1);
                suml0 += p0 + p1;
                suml1 += p2 + p3;
                __nv_bfloat16 h0 = __float2bfloat16_rn(p0), h1 = __float2bfloat16_rn(p1);
                __nv_bfloat16 h2 = __float2bfloat16_rn(p2), h3 = __float2bfloat16_rn(p3);
                ph[kt][half * 2 + 0] = packbf(h0, h1);
                ph[kt][half * 2 + 1] = packbf(h2, h3);
                pl[kt][half * 2 + 0] = packbf(
                    __float2bfloat16_rn(p0 - __bfloat162float(h0)),
                    __float2bfloat16_rn(p1 - __bfloat162float(h1)));
                pl[kt][half * 2 + 1] = packbf(
                    __float2bfloat16_rn(p2 - __bfloat162float(h2)),
                    __float2bfloat16_rn(p3 - __bfloat162float(h3)));
            }
        }
        l0 = l0 * corr0 + suml0;
        l1 = l1 * corr1 + suml1;

        #pragma unroll
        for (int nt = 0; nt < 8; nt++) {
            acc_o[nt][0] *= corr0;
            acc_o[nt][1] *= corr0;
            acc_o[nt][2] *= corr1;
            acc_o[nt][3] *= corr1;
        }

        // ---- O += P V (split) ----
        #pragma unroll
        for (int kt = 0; kt < 4; kt++) {
            #pragma unroll
            for (int nc = 0; nc < 4; nc++) {
                uint32_t vh[4], vl[4];
                ldsm4t(smem_u32(&Vs[0][kt * 16 + vb_krow][nc * 16 + vb_noff]), vh);
                ldsm4t(smem_u32(&Vs[1][kt * 16 + vb_krow][nc * 16 + vb_noff]), vl);
                mma16816(acc_o[2 * nc],     ph[kt], vh[0], vh[1]);
                mma16816(acc_o[2 * nc],     pl[kt], vh[0], vh[1]);
                mma16816(acc_o[2 * nc],     ph[kt], vl[0], vl[1]);
                mma16816(acc_o[2 * nc + 1], ph[kt], vh[2], vh[3]);
                mma16816(acc_o[2 * nc + 1], pl[kt], vh[2], vh[3]);
                mma16816(acc_o[2 * nc + 1], ph[kt], vl[2], vl[3]);
            }
        }
        __syncthreads();   // all warps done reading before next tile's cp.async
    }

    // ---- epilogue: finish l, normalize, write bf16 hi/lo attn output ----
    l0 += __shfl_xor_sync(0xffffffffu, l0, 1);
    l0 += __shfl_xor_sync(0xffffffffu, l0, 2);
    l1 += __shfl_xor_sync(0xffffffffu, l1, 1);
    l1 += __shfl_xor_sync(0xffffffffu, l1, 2);
    float inv0 = 1.f / l0, inv1 = 1.f / l1;

    size_t r0off = ((size_t)(bb * S_ + i0)) * DM + h * DK;
    size_t r1off = r0off + (size_t)8 * DM;
    #pragma unroll
    for (int nt = 0; nt < 8; nt++) {
        int d = nt * 8 + tig * 2;
        store_split(g_ah, g_al, r0off + d, acc_o[nt][0] * inv0, acc_o[nt][1] * inv0);
        store_split(g_ah, g_al, r1off + d, acc_o[nt][2] * inv1, acc_o[nt][3] * inv1);
    }
}

// ---------------------------------------------------------------------------
extern "C" void kernel_launch(void* const* d_in, const int* in_sizes, int n_in,
                              void* d_out, int out_size) {
    const float* x     = (const float*)d_in[0];   // [2,2048,1024]
    const float* w_qkv = (const float*)d_in[1];   // [1024,3072]
    const float* w_o   = (const float*)d_in[2];   // [1024,1024]
    float* out = (float*)d_out;                   // [2,2048,1024]

    __nv_bfloat16 *xh, *xl, *wqh, *wql, *woh, *wol;
    cudaGetSymbolAddress((void**)&xh,  g_xh);
    cudaGetSymbolAddress((void**)&xl,  g_xl);
    cudaGetSymbolAddress((void**)&wqh, g_wqh);
    cudaGetSymbolAddress((void**)&wql, g_wql);
    cudaGetSymbolAddress((void**)&woh, g_woh);
    cudaGetSymbolAddress((void**)&wol, g_wol);

    // 0) hi/lo bf16 splits of x and weights
    split_kernel<<<MTOT * DM / 1024, 256>>>(x, xh, xl, MTOT * DM);
    split_kernel<<<DM * 3 * DM / 1024, 256>>>(w_qkv, wqh, wql, DM * 3 * DM);
    split_kernel<<<DM * DM / 1024, 256>>>(w_o, woh, wol, DM * DM);

    // 1) QKV projection (tensor core) + RoPE + bf16 hi/lo q/k/v
    {
        dim3 grid(3 * DM / BN, MTOT / BM);   // (48, 32)
        qkv_mma_rope<<<grid, 256>>>();
    }
    // 2) Sliding-window attention (tensor core), writes g_ah/g_al
    {
        dim3 grid(S_ / 64, NH, B_);          // (32, 16, 2)
        attn_mma<<<grid, 128>>>();
    }
    // 3) Output projection (tensor core)
    {
        dim3 grid(DM / BN, MTOT / BM);       // (16, 32)
        oproj_mma<<<grid, 256>>>(out);
    }
}

// round 13
// speedup vs baseline: 3.9839x; 1.0609x over previous
#include <cuda_runtime.h>
#include <cuda_bf16.h>
#include <math.h>
#include <stdint.h>

#define B_  2
#define S_  2048
#define DM  1024
#define NH  16
#define DK  64
#define WIN 512
#define MTOT (B_*S_)   // 4096

// bf16 hi/lo split scratch (allocation-free rule: __device__ globals)
__device__ __nv_bfloat16 g_xh[MTOT*DM],   g_xl[MTOT*DM];
__device__ __nv_bfloat16 g_wqh[DM*3*DM],  g_wql[DM*3*DM];
__device__ __nv_bfloat16 g_woh[DM*DM],    g_wol[DM*DM];
__device__ __nv_bfloat16 g_ah[MTOT*DM],   g_al[MTOT*DM];
// q/k/v in [B,H,S,DK], bf16 hi/lo (q pre-scaled by 1/8, rope applied)
__device__ __nv_bfloat16 g_qh[B_*NH*S_*DK], g_ql[B_*NH*S_*DK];
__device__ __nv_bfloat16 g_kh[B_*NH*S_*DK], g_kl[B_*NH*S_*DK];
__device__ __nv_bfloat16 g_vh[B_*NH*S_*DK], g_vl[B_*NH*S_*DK];

// ---------------------------------------------------------------------------
// helpers
// ---------------------------------------------------------------------------
__device__ __forceinline__ unsigned smem_u32(const void* p) {
    return (unsigned)__cvta_generic_to_shared(p);
}
#define CP_ASYNC16(dst_u32, src_ptr) \
    asm volatile("cp.async.cg.shared.global [%0], [%1], 16;\n" :: "r"(dst_u32), "l"(src_ptr))
#define CP_COMMIT() asm volatile("cp.async.commit_group;\n" ::: "memory")

__device__ __forceinline__ void ldsm4(uint32_t a, uint32_t* r) {
    asm volatile("ldmatrix.sync.aligned.m8n8.x4.shared.b16 {%0,%1,%2,%3}, [%4];\n"
        : "=r"(r[0]), "=r"(r[1]), "=r"(r[2]), "=r"(r[3]) : "r"(a));
}
__device__ __forceinline__ void ldsm4t(uint32_t a, uint32_t* r) {
    asm volatile("ldmatrix.sync.aligned.m8n8.x4.trans.shared.b16 {%0,%1,%2,%3}, [%4];\n"
        : "=r"(r[0]), "=r"(r[1]), "=r"(r[2]), "=r"(r[3]) : "r"(a));
}
__device__ __forceinline__ void mma16816(float* c, const uint32_t* a, uint32_t b0, uint32_t b1) {
    asm volatile("mma.sync.aligned.m16n8k16.row.col.f32.bf16.bf16.f32 "
        "{%0,%1,%2,%3}, {%4,%5,%6,%7}, {%8,%9}, {%0,%1,%2,%3};\n"
        : "+f"(c[0]), "+f"(c[1]), "+f"(c[2]), "+f"(c[3])
        : "r"(a[0]), "r"(a[1]), "r"(a[2]), "r"(a[3]), "r"(b0), "r"(b1));
}
__device__ __forceinline__ uint32_t packbf(__nv_bfloat16 a, __nv_bfloat16 b) {
    __nv_bfloat162 t(a, b);
    return *(uint32_t*)&t;
}
__device__ __forceinline__ void store_split(__nv_bfloat16* hi, __nv_bfloat16* lo,
                                            size_t idx, float x, float y) {
    __nv_bfloat16 hx = __float2bfloat16_rn(x), hy = __float2bfloat16_rn(y);
    __nv_bfloat16 lx = __float2bfloat16_rn(x - __bfloat162float(hx));
    __nv_bfloat16 ly = __float2bfloat16_rn(y - __bfloat162float(hy));
    *(__nv_bfloat162*)(hi + idx) = __nv_bfloat162(hx, hy);
    *(__nv_bfloat162*)(lo + idx) = __nv_bfloat162(lx, ly);
}

// ---------------------------------------------------------------------------
// fp32 -> (hi, lo) bf16 split, 4 elements per thread
// ---------------------------------------------------------------------------
__global__ __launch_bounds__(256)
void split_kernel(const float* __restrict__ src,
                  __nv_bfloat16* __restrict__ hi,
                  __nv_bfloat16* __restrict__ lo, int n) {
    int i = (blockIdx.x * 256 + threadIdx.x) * 4;
    if (i >= n) return;
    float4 v = *(const float4*)(src + i);
    store_split(hi, lo, i,     v.x, v.y);
    store_split(hi, lo, i + 2, v.z, v.w);
}

// ---------------------------------------------------------------------------
// Tensor-core GEMM: C = Ah*Bh + Ah*Bl + Al*Bh  (fp32 accum)
// Block tile 128x128, BK=16, 256 threads = 8 warps (4M x 2N), warp 32x64.
// ---------------------------------------------------------------------------
#define BM 128
#define BN 128
#define BKT 16
#define APAD 8    // A row stride 24 bf16 = 48B
#define BPAD 8    // B row stride 136 bf16 = 272B

__device__ __forceinline__ void mma_mainloop(
    const __nv_bfloat16* __restrict__ Ah, const __nv_bfloat16* __restrict__ Al,
    const __nv_bfloat16* __restrict__ Bh, const __nv_bfloat16* __restrict__ Bl,
    int m0, int n0, int N,
    float acc[2][8][4],
    __nv_bfloat16 (*As)[2][BM][BKT + APAD],
    __nv_bfloat16 (*Bs)[2][BKT][BN + BPAD])
{
    const int K = DM;
    const int tid  = threadIdx.x;
    const int lane = tid & 31;
    const int wid  = tid >> 5;
    const int wx   = wid & 1;    // N warp: 0..1 (64 cols)
    const int wy   = wid >> 1;   // M warp: 0..3 (32 rows)

    const int a_lrow = lane & 15;
    const int a_lcol = (lane >> 4) * 8;
    const int b_krow = ((lane >> 3) & 1) * 8 + (lane & 7);
    const int b_noff = ((lane >> 4) & 1) * 8;

    auto load_tile = [&](int buf, int kt) {
        #pragma unroll
        for (int it = 0; it < 2; it++) {
            int c   = tid + it * 256;          // 0..511
            int sp  = c >> 8;
            int rem = c & 255;
            int row = rem >> 1;                // 0..127
            int col = (rem & 1) * 8;           // 0 or 8
            const __nv_bfloat16* Ap = sp ? Al : Ah;
            CP_ASYNC16(smem_u32(&As[buf][sp][row][col]),
                       Ap + (size_t)(m0 + row) * K + kt + col);
        }
        #pragma unroll
        for (int it = 0; it < 2; it++) {
            int c   = tid + it * 256;
            int sp  = c >> 8;
            int rem = c & 255;
            int r   = rem >> 4;                // 0..15
            int col = (rem & 15) * 8;          // 0..120
            const __nv_bfloat16* Bp = sp ? Bl : Bh;
            CP_ASYNC16(smem_u32(&Bs[buf][sp][r][col]),
                       Bp + (size_t)(kt + r) * N + n0 + col);
        }
    };

    load_tile(0, 0);
    CP_COMMIT();

    int buf = 0;
    for (int kt = 0; kt < K; kt += BKT, buf ^= 1) {
        const bool has_next = (kt + BKT) < K;
        if (has_next) {
            load_tile(buf ^ 1, kt + BKT);
            CP_COMMIT();
            asm volatile("cp.async.wait_group 1;\n" ::: "memory");
        } else {
            asm volatile("cp.async.wait_group 0;\n" ::: "memory");
        }
        __syncthreads();

        // A fragments (hi/lo, 2 m16 tiles)
        uint32_t af[2][2][4];
        #pragma unroll
        for (int sp = 0; sp < 2; sp++)
            #pragma unroll
            for (int mi = 0; mi < 2; mi++)
                ldsm4(smem_u32(&As[buf][sp][wy * 32 + mi * 16 + a_lrow][a_lcol]),
                      af[sp][mi]);

        // B per-nj: load 8 regs, fire 12 MMAs, keep register pressure low
        #pragma unroll
        for (int nj = 0; nj < 4; nj++) {
            uint32_t bh[4], bl[4];
            ldsm4t(smem_u32(&Bs[buf][0][b_krow][wx * 64 + nj * 16 + b_noff]), bh);
            ldsm4t(smem_u32(&Bs[buf][1][b_krow][wx * 64 + nj * 16 + b_noff]), bl);
            #pragma unroll
            for (int mi = 0; mi < 2; mi++) {
                float* c0 = acc[mi][2 * nj];
                float* c1 = acc[mi][2 * nj + 1];
                mma16816(c0, af[0][mi], bh[0], bh[1]);
                mma16816(c0, af[0][mi], bl[0], bl[1]);
                mma16816(c0, af[1][mi], bh[0], bh[1]);
                mma16816(c1, af[0][mi], bh[2], bh[3]);
                mma16816(c1, af[0][mi], bl[2], bl[3]);
                mma16816(c1, af[1][mi], bh[2], bh[3]);
            }
        }
        __syncthreads();
    }
}

// Kernel 1: qkv = x @ w_qkv; epilogue applies RoPE (+1/8 scale on q) and
// writes bf16 hi/lo q/k/v directly.
__global__ __launch_bounds__(256, 2)
void qkv_mma_rope() {
    __shared__ __align__(16) __nv_bfloat16 As[2][2][BM][BKT + APAD];
    __shared__ __align__(16) __nv_bfloat16 Bs[2][2][BKT][BN + BPAD];

    const int m0 = blockIdx.y * BM;
    const int n0 = blockIdx.x * BN;

    float acc[2][8][4];
    #pragma unroll
    for (int mi = 0; mi < 2; mi++)
        #pragma unroll
        for (int ni = 0; ni < 8; ni++)
            #pragma unroll
            for (int r = 0; r < 4; r++) acc[mi][ni][r] = 0.f;

    mma_mainloop(g_xh, g_xl, g_wqh, g_wql, m0, n0, 3 * DM, acc, As, Bs);

    const int lane = threadIdx.x & 31;
    const int wid  = threadIdx.x >> 5;
    const int wx   = wid & 1;
    const int wy   = wid >> 1;
    const int g    = lane >> 2;
    const int tig  = lane & 3;

    const int which = n0 >> 10;            // constant per block (n0 mult of 128)
    __nv_bfloat16* hb = (which == 0) ? g_qh : (which == 1) ? g_kh : g_vh;
    __nv_bfloat16* lb = (which == 0) ? g_ql : (which == 1) ? g_kl : g_vl;
    const float qscale = (which == 0) ? 0.125f : 1.0f;

    // per-ni head and rope frequency
    int   hh[8];
    int   dd[8];
    float invf[8];
    #pragma unroll
    for (int ni = 0; ni < 8; ni++) {
        int n_abs = n0 + wx * 64 + ni * 8 + tig * 2;
        hh[ni] = (n_abs & 1023) >> 6;
        dd[ni] = n_abs & 63;
        invf[ni] = powf(10000.0f, -(float)(dd[ni] >> 1) / 32.0f);
    }

    #pragma unroll
    for (int mi = 0; mi < 2; mi++) {
        #pragma unroll
        for (int half = 0; half < 2; half++) {
            int m = m0 + wy * 32 + mi * 16 + g + half * 8;
            int bb = m >> 11, s = m & 2047;
            float fs = (float)s;
            #pragma unroll
            for (int ni = 0; ni < 8; ni++) {
                size_t rowoff = ((size_t)(bb * NH + hh[ni]) * S_ + s) * DK + dd[ni];
                float e = acc[mi][ni][half * 2 + 0];
                float o = acc[mi][ni][half * 2 + 1];
                float ox, oy;
                if (which == 2) {
                    ox = e; oy = o;
                } else {
                    float sn, cs;
                    sincosf(fs * invf[ni], &sn, &cs);
                    ox = (e * cs - o * sn) * qscale;
                    oy = (o * cs + e * sn) * qscale;
                }
                store_split(hb, lb, rowoff, ox, oy);
            }
        }
    }
}

// Kernel 3: d_out = attn_out @ w_o
__global__ __launch_bounds__(256, 2)
void oproj_mma(float* __restrict__ C) {
    __shared__ __align__(16) __nv_bfloat16 As[2][2][BM][BKT + APAD];
    __shared__ __align__(16) __nv_bfloat16 Bs[2][2][BKT][BN + BPAD];

    const int m0 = blockIdx.y * BM;
    const int n0 = blockIdx.x * BN;

    float acc[2][8][4];
    #pragma unroll
    for (int mi = 0; mi < 2; mi++)
        #pragma unroll
        for (int ni = 0; ni < 8; ni++)
            #pragma unroll
            for (int r = 0; r < 4; r++) acc[mi][ni][r] = 0.f;

    mma_mainloop(g_ah, g_al, g_woh, g_wol, m0, n0, DM, acc, As, Bs);

    const int lane = threadIdx.x & 31;
    const int wid  = threadIdx.x >> 5;
    const int wx   = wid & 1;
    const int wy   = wid >> 1;
    const int g    = lane >> 2;
    const int tig  = lane & 3;

    #pragma unroll
    for (int mi = 0; mi < 2; mi++) {
        #pragma unroll
        for (int half = 0; half < 2; half++) {
            int m = m0 + wy * 32 + mi * 16 + g + half * 8;
            #pragma unroll
            for (int ni = 0; ni < 8; ni++) {
                int d = wx * 64 + ni * 8 + tig * 2;
                float2 out;
                out.x = acc[mi][ni][half * 2 + 0];
                out.y = acc[mi][ni][half * 2 + 1];
                *(float2*)(C + (size_t)m * DM + n0 + d) = out;
            }
        }
    }
}

// ---------------------------------------------------------------------------
// Kernel 2: sliding-window flash attention on tensor cores (unchanged).
// grid (S/64, H, B), 128 threads = 4 warps; warp w owns queries
// [qs + 16w, qs + 16w + 16). Key tiles of 64. hi/lo-split bf16 MMAs.
// ---------------------------------------------------------------------------
#define ATP 8

__global__ __launch_bounds__(128)
void attn_mma() {
    __shared__ __align__(16) __nv_bfloat16 Ks[2][64][64 + ATP];
    __shared__ __align__(16) __nv_bfloat16 Vs[2][64][64 + ATP];

    const int tid  = threadIdx.x;
    const int lane = tid & 31;
    const int w    = tid >> 5;
    const int g    = lane >> 2;
    const int tig  = lane & 3;
    const int qs   = blockIdx.x * 64;
    const int h    = blockIdx.y;
    const int bb   = blockIdx.z;

    const size_t base = ((size_t)(bb * NH + h)) * S_ * DK;

    #pragma unroll
    for (int it = 0; it < 8; it++) {
        int c   = tid + it * 128;
        int sp  = c >> 9;
        int rem = c & 511;
        int row = rem >> 3;
        int col = (rem & 7) * 8;
        const __nv_bfloat16* src = (sp ? g_ql : g_qh) + base + (size_t)(qs + row) * DK + col;
        CP_ASYNC16(smem_u32(&Ks[sp][row][col]), src);
    }
    CP_COMMIT();
    asm volatile("cp.async.wait_group 0;\n" ::: "memory");
    __syncthreads();

    const int a_lrow = lane & 15;
    const int a_lcol = (lane >> 4) * 8;
    uint32_t qa[2][4][4];
    #pragma unroll
    for (int sp = 0; sp < 2; sp++)
        #pragma unroll
        for (int kt = 0; kt < 4; kt++)
            ldsm4(smem_u32(&Ks[sp][w * 16 + a_lrow][kt * 16 + a_lcol]), qa[sp][kt]);
    __syncthreads();

    const int kb_t    = lane >> 3;
    const int kb_nrow = (kb_t & 1) * 8 + (lane & 7);
    const int kb_kcol = (kb_t >> 1) * 8;
    const int vb_krow = ((lane >> 3) & 1) * 8 + (lane & 7);
    const int vb_noff = ((lane >> 4) & 1) * 8;

    float m0 = -1e30f, m1 = -1e30f;
    float l0 = 0.f, l1 = 0.f;
    float acc_o[8][4];
    #pragma unroll
    for (int nt = 0; nt < 8; nt++)
        #pragma unroll
        for (int r = 0; r < 4; r++) acc_o[nt][r] = 0.f;

    const int i0 = qs + w * 16 + g;
    const int kc_start = (qs >= WIN) ? (qs - WIN) : 0;

    for (int kc = kc_start; kc <= qs; kc += 64) {
        #pragma unroll
        for (int it = 0; it < 16; it++) {
            int c   = tid + it * 128;
            int arr = c >> 9;
            int rem = c & 511;
            int row = rem >> 3;
            int col = (rem & 7) * 8;
            const __nv_bfloat16* src =
                (arr == 0 ? g_kh : arr == 1 ? g_kl : arr == 2 ? g_vh : g_vl)
                + base + (size_t)(kc + row) * DK + col;
            unsigned dst = (arr < 2) ? smem_u32(&Ks[arr][row][col])
                                     : smem_u32(&Vs[arr - 2][row][col]);
            CP_ASYNC16(dst, src);
        }
        CP_COMMIT();
        asm volatile("cp.async.wait_group 0;\n" ::: "memory");
        __syncthreads();

        float s[8][4];
        #pragma unroll
        for (int nt = 0; nt < 8; nt++)
            #pragma unroll
            for (int r = 0; r < 4; r++) s[nt][r] = 0.f;

        #pragma unroll
        for (int kt = 0; kt < 4; kt++) {
            #pragma unroll
            for (int nc = 0; nc < 4; nc++) {
                uint32_t kh[4], kl[4];
                ldsm4(smem_u32(&Ks[0][nc * 16 + kb_nrow][kt * 16 + kb_kcol]), kh);
                ldsm4(smem_u32(&Ks[1][nc * 16 + kb_nrow][kt * 16 + kb_kcol]), kl);
                mma16816(s[2 * nc],     qa[0][kt], kh[0], kh[2]);
                mma16816(s[2 * nc],     qa[0][kt], kl[0], kl[2]);
                mma16816(s[2 * nc],     qa[1][kt], kh[0], kh[2]);
                mma16816(s[2 * nc + 1], qa[0][kt], kh[1], kh[3]);
                mma16816(s[2 * nc + 1], qa[0][kt], kl[1], kl[3]);
                mma16816(s[2 * nc + 1], qa[1][kt], kh[1], kh[3]);
            }
        }

        if (kc == qs || kc + WIN == qs) {
            #pragma unroll
            for (int nt = 0; nt < 8; nt++) {
                int jb = kc + nt * 8 + tig * 2;
                #pragma unroll
                for (int r = 0; r < 4; r++) {
                    int j = jb + (r & 1);
                    int i = i0 + ((r >= 2) ? 8 : 0);
                    if (j > i || j < i - WIN) s[nt][r] = -1e30f;
                }
            }
        }

        float t0 = -1e30f, t1 = -1e30f;
        #pragma unroll
        for (int nt = 0; nt < 8; nt++) {
            t0 = fmaxf(t0, fmaxf(s[nt][0], s[nt][1]));
            t1 = fmaxf(t1, fmaxf(s[nt][2], s[nt][3]));
        }
        t0 = fmaxf(t0, __shfl_xor_sync(0xffffffffu, t0, 1));
        t0 = fmaxf(t0, __shfl_xor_sync(0xffffffffu, t0, 2));
        t1 = fmaxf(t1, __shfl_xor_sync(0xffffffffu, t1, 1));
        t1 = fmaxf(t1, __shfl_xor_sync(0xffffffffu, t1, 2));

        float mn0 = fmaxf(m0, t0), mn1 = fmaxf(m1, t1);
        float corr0 = __expf(m0 - mn0), corr1 = __expf(m1 - mn1);
        m0 = mn0; m1 = mn1;

        uint32_t ph[4][4], pl[4][4];
        float suml0 = 0.f, suml1 = 0.f;
        #pragma unroll
        for (int kt = 0; kt < 4; kt++) {
            #pragma unroll
            for (int half = 0; half < 2; half++) {
                int nt = 2 * kt + half;
                float p0 = __expf(s[nt][0] - m0);
                float p1 = __expf(s[nt][1] - m0);
                float p2 = __expf(s[nt][2] - m1);
                float p3 = __expf(s[nt][3] - m1);
                suml0 += p0 + p1;
                suml1 += p2 + p3;
                __nv_bfloat16 h0 = __float2bfloat16_rn(p0), h1 = __float2bfloat16_rn(p1);
                __nv_bfloat16 h2 = __float2bfloat16_rn(p2), h3 = __float2bfloat16_rn(p3);
                ph[kt][half * 2 + 0] = packbf(h0, h1);
                ph[kt][half * 2 + 1] = packbf(h2, h3);
                pl[kt][half * 2 + 0] = packbf(
                    __float2bfloat16_rn(p0 - __bfloat162float(h0)),
                    __float2bfloat16_rn(p1 - __bfloat162float(h1)));
                pl[kt][half * 2 + 1] = packbf(
                    __float2bfloat16_rn(p2 - __bfloat162float(h2)),
                    __float2bfloat16_rn(p3 - __bfloat162float(h3)));
            }
        }
        l0 = l0 * corr0 + suml0;
        l1 = l1 * corr1 + suml1;

        #pragma unroll
        for (int nt = 0; nt < 8; nt++) {
            acc_o[nt][0] *= corr0;
            acc_o[nt][1] *= corr0;
            acc_o[nt][2] *= corr1;
            acc_o[nt][3] *= corr1;
        }

        #pragma unroll
        for (int kt = 0; kt < 4; kt++) {
            #pragma unroll
            for (int nc = 0; nc < 4; nc++) {
                uint32_t vh[4], vl[4];
                ldsm4t(smem_u32(&Vs[0][kt * 16 + vb_krow][nc * 16 + vb_noff]), vh);
                ldsm4t(smem_u32(&Vs[1][kt * 16 + vb_krow][nc * 16 + vb_noff]), vl);
                mma16816(acc_o[2 * nc],     ph[kt], vh[0], vh[1]);
                mma16816(acc_o[2 * nc],     pl[kt], vh[0], vh[1]);
                mma16816(acc_o[2 * nc],     ph[kt], vl[0], vl[1]);
                mma16816(acc_o[2 * nc + 1], ph[kt], vh[2], vh[3]);
                mma16816(acc_o[2 * nc + 1], pl[kt], vh[2], vh[3]);
                mma16816(acc_o[2 * nc + 1], ph[kt], vl[2], vl[3]);
            }
        }
        __syncthreads();
    }

    l0 += __shfl_xor_sync(0xffffffffu, l0, 1);
    l0 += __shfl_xor_sync(0xffffffffu, l0, 2);
    l1 += __shfl_xor_sync(0xffffffffu, l1, 1);
    l1 += __shfl_xor_sync(0xffffffffu, l1, 2);
    float inv0 = 1.f / l0, inv1 = 1.f / l1;

    size_t r0off = ((size_t)(bb * S_ + i0)) * DM + h * DK;
    size_t r1off = r0off + (size_t)8 * DM;
    #pragma unroll
    for (int nt = 0; nt < 8; nt++) {
        int d = nt * 8 + tig * 2;
        store_split(g_ah, g_al, r0off + d, acc_o[nt][0] * inv0, acc_o[nt][1] * inv0);
        store_split(g_ah, g_al, r1off + d, acc_o[nt][2] * inv1, acc_o[nt][3] * inv1);
    }
}

// ---------------------------------------------------------------------------
extern "C" void kernel_launch(void* const* d_in, const int* in_sizes, int n_in,
                              void* d_out, int out_size) {
    const float* x     = (const float*)d_in[0];   // [2,2048,1024]
    const float* w_qkv = (const float*)d_in[1];   // [1024,3072]
    const float* w_o   = (const float*)d_in[2];   // [1024,1024]
    float* out = (float*)d_out;                   // [2,2048,1024]

    __nv_bfloat16 *xh, *xl, *wqh, *wql, *woh, *wol;
    cudaGetSymbolAddress((void**)&xh,  g_xh);
    cudaGetSymbolAddress((void**)&xl,  g_xl);
    cudaGetSymbolAddress((void**)&wqh, g_wqh);
    cudaGetSymbolAddress((void**)&wql, g_wql);
    cudaGetSymbolAddress((void**)&woh, g_woh);
    cudaGetSymbolAddress((void**)&wol, g_wol);

    // 0) hi/lo bf16 splits of x and weights
    split_kernel<<<MTOT * DM / 1024, 256>>>(x, xh, xl, MTOT * DM);
    split_kernel<<<DM * 3 * DM / 1024, 256>>>(w_qkv, wqh, wql, DM * 3 * DM);
    split_kernel<<<DM * DM / 1024, 256>>>(w_o, woh, wol, DM * DM);

    // 1) QKV projection (tensor core) + RoPE + bf16 hi/lo q/k/v
    {
        dim3 grid(3 * DM / BN, MTOT / BM);   // (24, 32)
        qkv_mma_rope<<<grid, 256>>>();
    }
    // 2) Sliding-window attention (tensor core), writes g_ah/g_al
    {
        dim3 grid(S_ / 64, NH, B_);          // (32, 16, 2)
        attn_mma<<<grid, 128>>>();
    }
    // 3) Output projection (tensor core)
    {
        dim3 grid(DM / BN, MTOT / BM);       // (8, 32)
        oproj_mma<<<grid, 256>>>(out);
    }
}

// round 17
// speedup vs baseline: 3.9946x; 1.0027x over previous
#include <cuda_runtime.h>
#include <cuda_bf16.h>
#include <math.h>
#include <stdint.h>

#define B_  2
#define S_  2048
#define DM  1024
#define NH  16
#define DK  64
#define WIN 512
#define MTOT (B_*S_)   // 4096

// bf16 hi/lo split scratch (allocation-free rule: __device__ globals)
__device__ __nv_bfloat16 g_xh[MTOT*DM],   g_xl[MTOT*DM];
__device__ __nv_bfloat16 g_wqh[DM*3*DM],  g_wql[DM*3*DM];
__device__ __nv_bfloat16 g_woh[DM*DM],    g_wol[DM*DM];
__device__ __nv_bfloat16 g_ah[MTOT*DM],   g_al[MTOT*DM];
// q/k/v in [B,H,S,DK], bf16 hi/lo (q pre-scaled by 1/8, rope applied)
__device__ __nv_bfloat16 g_qh[B_*NH*S_*DK], g_ql[B_*NH*S_*DK];
__device__ __nv_bfloat16 g_kh[B_*NH*S_*DK], g_kl[B_*NH*S_*DK];
__device__ __nv_bfloat16 g_vh[B_*NH*S_*DK], g_vl[B_*NH*S_*DK];

// ---------------------------------------------------------------------------
// helpers
// ---------------------------------------------------------------------------
__device__ __forceinline__ unsigned smem_u32(const void* p) {
    return (unsigned)__cvta_generic_to_shared(p);
}
#define CP_ASYNC16(dst_u32, src_ptr) \
    asm volatile("cp.async.cg.shared.global [%0], [%1], 16;\n" :: "r"(dst_u32), "l"(src_ptr))
#define CP_COMMIT() asm volatile("cp.async.commit_group;\n" ::: "memory")

__device__ __forceinline__ void ldsm4(uint32_t a, uint32_t* r) {
    asm volatile("ldmatrix.sync.aligned.m8n8.x4.shared.b16 {%0,%1,%2,%3}, [%4];\n"
        : "=r"(r[0]), "=r"(r[1]), "=r"(r[2]), "=r"(r[3]) : "r"(a));
}
__device__ __forceinline__ void ldsm4t(uint32_t a, uint32_t* r) {
    asm volatile("ldmatrix.sync.aligned.m8n8.x4.trans.shared.b16 {%0,%1,%2,%3}, [%4];\n"
        : "=r"(r[0]), "=r"(r[1]), "=r"(r[2]), "=r"(r[3]) : "r"(a));
}
__device__ __forceinline__ void mma16816(float* c, const uint32_t* a, uint32_t b0, uint32_t b1) {
    asm volatile("mma.sync.aligned.m16n8k16.row.col.f32.bf16.bf16.f32 "
        "{%0,%1,%2,%3}, {%4,%5,%6,%7}, {%8,%9}, {%0,%1,%2,%3};\n"
        : "+f"(c[0]), "+f"(c[1]), "+f"(c[2]), "+f"(c[3])
        : "r"(a[0]), "r"(a[1]), "r"(a[2]), "r"(a[3]), "r"(b0), "r"(b1));
}
__device__ __forceinline__ uint32_t packbf(__nv_bfloat16 a, __nv_bfloat16 b) {
    __nv_bfloat162 t(a, b);
    return *(uint32_t*)&t;
}
__device__ __forceinline__ void store_split(__nv_bfloat16* hi, __nv_bfloat16* lo,
                                            size_t idx, float x, float y) {
    __nv_bfloat16 hx = __float2bfloat16_rn(x), hy = __float2bfloat16_rn(y);
    __nv_bfloat16 lx = __float2bfloat16_rn(x - __bfloat162float(hx));
    __nv_bfloat16 ly = __float2bfloat16_rn(y - __bfloat162float(hy));
    *(__nv_bfloat162*)(hi + idx) = __nv_bfloat162(hx, hy);
    *(__nv_bfloat162*)(lo + idx) = __nv_bfloat162(lx, ly);
}

// ---------------------------------------------------------------------------
// fp32 -> (hi, lo) bf16 split, 4 elements per thread
// ---------------------------------------------------------------------------
__global__ __launch_bounds__(256)
void split_kernel(const float* __restrict__ src,
                  __nv_bfloat16* __restrict__ hi,
                  __nv_bfloat16* __restrict__ lo, int n) {
    int i = (blockIdx.x * 256 + threadIdx.x) * 4;
    if (i >= n) return;
    float4 v = *(const float4*)(src + i);
    store_split(hi, lo, i,     v.x, v.y);
    store_split(hi, lo, i + 2, v.z, v.w);
}

// ---------------------------------------------------------------------------
// Tensor-core GEMM: C = Ah*Bh + Ah*Bl + Al*Bh  (fp32 accum)
// Block tile 128x128, BK=16, 256 threads = 8 warps (4M x 2N), warp 32x64.
// MMA emission interleaved across 4 independent accumulator chains.
// ---------------------------------------------------------------------------
#define BM 128
#define BN 128
#define BKT 16
#define APAD 8    // A row stride 24 bf16 = 48B
#define BPAD 8    // B row stride 136 bf16 = 272B

__device__ __forceinline__ void mma_mainloop(
    const __nv_bfloat16* __restrict__ Ah, const __nv_bfloat16* __restrict__ Al,
    const __nv_bfloat16* __restrict__ Bh, const __nv_bfloat16* __restrict__ Bl,
    int m0, int n0, int N,
    float acc[2][8][4],
    __nv_bfloat16 (*As)[2][BM][BKT + APAD],
    __nv_bfloat16 (*Bs)[2][BKT][BN + BPAD])
{
    const int K = DM;
    const int tid  = threadIdx.x;
    const int lane = tid & 31;
    const int wid  = tid >> 5;
    const int wx   = wid & 1;    // N warp: 0..1 (64 cols)
    const int wy   = wid >> 1;   // M warp: 0..3 (32 rows)

    const int a_lrow = lane & 15;
    const int a_lcol = (lane >> 4) * 8;
    const int b_krow = ((lane >> 3) & 1) * 8 + (lane & 7);
    const int b_noff = ((lane >> 4) & 1) * 8;

    auto load_tile = [&](int buf, int kt) {
        #pragma unroll
        for (int it = 0; it < 2; it++) {
            int c   = tid + it * 256;          // 0..511
            int sp  = c >> 8;
            int rem = c & 255;
            int row = rem >> 1;                // 0..127
            int col = (rem & 1) * 8;           // 0 or 8
            const __nv_bfloat16* Ap = sp ? Al : Ah;
            CP_ASYNC16(smem_u32(&As[buf][sp][row][col]),
                       Ap + (size_t)(m0 + row) * K + kt + col);
        }
        #pragma unroll
        for (int it = 0; it < 2; it++) {
            int c   = tid + it * 256;
            int sp  = c >> 8;
            int rem = c & 255;
            int r   = rem >> 4;                // 0..15
            int col = (rem & 15) * 8;          // 0..120
            const __nv_bfloat16* Bp = sp ? Bl : Bh;
            CP_ASYNC16(smem_u32(&Bs[buf][sp][r][col]),
                       Bp + (size_t)(kt + r) * N + n0 + col);
        }
    };

    load_tile(0, 0);
    CP_COMMIT();

    int buf = 0;
    for (int kt = 0; kt < K; kt += BKT, buf ^= 1) {
        const bool has_next = (kt + BKT) < K;
        if (has_next) {
            load_tile(buf ^ 1, kt + BKT);
            CP_COMMIT();
            asm volatile("cp.async.wait_group 1;\n" ::: "memory");
        } else {
            asm volatile("cp.async.wait_group 0;\n" ::: "memory");
        }
        __syncthreads();

        // A fragments (hi/lo, 2 m16 tiles)
        uint32_t af[2][2][4];
        #pragma unroll
        for (int sp = 0; sp < 2; sp++)
            #pragma unroll
            for (int mi = 0; mi < 2; mi++)
                ldsm4(smem_u32(&As[buf][sp][wy * 32 + mi * 16 + a_lrow][a_lcol]),
                      af[sp][mi]);

        // B per-nj group; MMAs emitted round-robin over the 4 independent
        // accumulator chains (mi x {c0,c1}) so dependent MMAs are distance 4.
        #pragma unroll
        for (int nj = 0; nj < 4; nj++) {
            uint32_t bh[4], bl[4];
            ldsm4t(smem_u32(&Bs[buf][0][b_krow][wx * 64 + nj * 16 + b_noff]), bh);
            ldsm4t(smem_u32(&Bs[buf][1][b_krow][wx * 64 + nj * 16 + b_noff]), bl);
            float* c00 = acc[0][2 * nj];
            float* c01 = acc[0][2 * nj + 1];
            float* c10 = acc[1][2 * nj];
            float* c11 = acc[1][2 * nj + 1];
            // round 1: hi*hi
            mma16816(c00, af[0][0], bh[0], bh[1]);
            mma16816(c01, af[0][0], bh[2], bh[3]);
            mma16816(c10, af[0][1], bh[0], bh[1]);
            mma16816(c11, af[0][1], bh[2], bh[3]);
            // round 2: hi*lo
            mma16816(c00, af[0][0], bl[0], bl[1]);
            mma16816(c01, af[0][0], bl[2], bl[3]);
            mma16816(c10, af[0][1], bl[0], bl[1]);
            mma16816(c11, af[0][1], bl[2], bl[3]);
            // round 3: lo*hi
            mma16816(c00, af[1][0], bh[0], bh[1]);
            mma16816(c01, af[1][0], bh[2], bh[3]);
            mma16816(c10, af[1][1], bh[0], bh[1]);
            mma16816(c11, af[1][1], bh[2], bh[3]);
        }
        __syncthreads();
    }
}

// Kernel 1: qkv = x @ w_qkv; epilogue applies RoPE (+1/8 scale on q) and
// writes bf16 hi/lo q/k/v directly.
__global__ __launch_bounds__(256, 2)
void qkv_mma_rope() {
    __shared__ __align__(16) __nv_bfloat16 As[2][2][BM][BKT + APAD];
    __shared__ __align__(16) __nv_bfloat16 Bs[2][2][BKT][BN + BPAD];

    const int m0 = blockIdx.y * BM;
    const int n0 = blockIdx.x * BN;

    float acc[2][8][4];
    #pragma unroll
    for (int mi = 0; mi < 2; mi++)
        #pragma unroll
        for (int ni = 0; ni < 8; ni++)
            #pragma unroll
            for (int r = 0; r < 4; r++) acc[mi][ni][r] = 0.f;

    mma_mainloop(g_xh, g_xl, g_wqh, g_wql, m0, n0, 3 * DM, acc, As, Bs);

    const int lane = threadIdx.x & 31;
    const int wid  = threadIdx.x >> 5;
    const int wx   = wid & 1;
    const int wy   = wid >> 1;
    const int g    = lane >> 2;
    const int tig  = lane & 3;

    const int which = n0 >> 10;            // constant per block (n0 mult of 128)
    __nv_bfloat16* hb = (which == 0) ? g_qh : (which == 1) ? g_kh : g_vh;
    __nv_bfloat16* lb = (which == 0) ? g_ql : (which == 1) ? g_kl : g_vl;
    const float qscale = (which == 0) ? 0.125f : 1.0f;

    // per-ni head and rope frequency
    int   hh[8];
    int   dd[8];
    float invf[8];
    #pragma unroll
    for (int ni = 0; ni < 8; ni++) {
        int n_abs = n0 + wx * 64 + ni * 8 + tig * 2;
        hh[ni] = (n_abs & 1023) >> 6;
        dd[ni] = n_abs & 63;
        invf[ni] = powf(10000.0f, -(float)(dd[ni] >> 1) / 32.0f);
    }

    #pragma unroll
    for (int mi = 0; mi < 2; mi++) {
        #pragma unroll
        for (int half = 0; half < 2; half++) {
            int m = m0 + wy * 32 + mi * 16 + g + half * 8;
            int bb = m >> 11, s = m & 2047;
            float fs = (float)s;
            #pragma unroll
            for (int ni = 0; ni < 8; ni++) {
                size_t rowoff = ((size_t)(bb * NH + hh[ni]) * S_ + s) * DK + dd[ni];
                float e = acc[mi][ni][half * 2 + 0];
                float o = acc[mi][ni][half * 2 + 1];
                float ox, oy;
                if (which == 2) {
                    ox = e; oy = o;
                } else {
                    float sn, cs;
                    sincosf(fs * invf[ni], &sn, &cs);
                    ox = (e * cs - o * sn) * qscale;
                    oy = (o * cs + e * sn) * qscale;
                }
                store_split(hb, lb, rowoff, ox, oy);
            }
        }
    }
}

// Kernel 3: d_out = attn_out @ w_o
__global__ __launch_bounds__(256, 2)
void oproj_mma(float* __restrict__ C) {
    __shared__ __align__(16) __nv_bfloat16 As[2][2][BM][BKT + APAD];
    __shared__ __align__(16) __nv_bfloat16 Bs[2][2][BKT][BN + BPAD];

    const int m0 = blockIdx.y * BM;
    const int n0 = blockIdx.x * BN;

    float acc[2][8][4];
    #pragma unroll
    for (int mi = 0; mi < 2; mi++)
        #pragma unroll
        for (int ni = 0; ni < 8; ni++)
            #pragma unroll
            for (int r = 0; r < 4; r++) acc[mi][ni][r] = 0.f;

    mma_mainloop(g_ah, g_al, g_woh, g_wol, m0, n0, DM, acc, As, Bs);

    const int lane = threadIdx.x & 31;
    const int wid  = threadIdx.x >> 5;
    const int wx   = wid & 1;
    const int wy   = wid >> 1;
    const int g    = lane >> 2;
    const int tig  = lane & 3;

    #pragma unroll
    for (int mi = 0; mi < 2; mi++) {
        #pragma unroll
        for (int half = 0; half < 2; half++) {
            int m = m0 + wy * 32 + mi * 16 + g + half * 8;
            #pragma unroll
            for (int ni = 0; ni < 8; ni++) {
                int d = wx * 64 + ni * 8 + tig * 2;
                float2 out;
                out.x = acc[mi][ni][half * 2 + 0];
                out.y = acc[mi][ni][half * 2 + 1];
                *(float2*)(C + (size_t)m * DM + n0 + d) = out;
            }
        }
    }
}

// ---------------------------------------------------------------------------
// Kernel 2: sliding-window flash attention on tensor cores.
// grid (S/64, H, B), 128 threads = 4 warps; warp w owns queries
// [qs + 16w, qs + 16w + 16). Key tiles of 64. hi/lo-split bf16 MMAs.
// MMA chains interleaved (distance 2) in QK^T and P.V loops.
// ---------------------------------------------------------------------------
#define ATP 8

__global__ __launch_bounds__(128)
void attn_mma() {
    __shared__ __align__(16) __nv_bfloat16 Ks[2][64][64 + ATP];
    __shared__ __align__(16) __nv_bfloat16 Vs[2][64][64 + ATP];

    const int tid  = threadIdx.x;
    const int lane = tid & 31;
    const int w    = tid >> 5;
    const int g    = lane >> 2;
    const int tig  = lane & 3;
    const int qs   = blockIdx.x * 64;
    const int h    = blockIdx.y;
    const int bb   = blockIdx.z;

    const size_t base = ((size_t)(bb * NH + h)) * S_ * DK;

    #pragma unroll
    for (int it = 0; it < 8; it++) {
        int c   = tid + it * 128;
        int sp  = c >> 9;
        int rem = c & 511;
        int row = rem >> 3;
        int col = (rem & 7) * 8;
        const __nv_bfloat16* src = (sp ? g_ql : g_qh) + base + (size_t)(qs + row) * DK + col;
        CP_ASYNC16(smem_u32(&Ks[sp][row][col]), src);
    }
    CP_COMMIT();
    asm volatile("cp.async.wait_group 0;\n" ::: "memory");
    __syncthreads();

    const int a_lrow = lane & 15;
    const int a_lcol = (lane >> 4) * 8;
    uint32_t qa[2][4][4];
    #pragma unroll
    for (int sp = 0; sp < 2; sp++)
        #pragma unroll
        for (int kt = 0; kt < 4; kt++)
            ldsm4(smem_u32(&Ks[sp][w * 16 + a_lrow][kt * 16 + a_lcol]), qa[sp][kt]);
    __syncthreads();

    const int kb_t    = lane >> 3;
    const int kb_nrow = (kb_t & 1) * 8 + (lane & 7);
    const int kb_kcol = (kb_t >> 1) * 8;
    const int vb_krow = ((lane >> 3) & 1) * 8 + (lane & 7);
    const int vb_noff = ((lane >> 4) & 1) * 8;

    float m0 = -1e30f, m1 = -1e30f;
    float l0 = 0.f, l1 = 0.f;
    float acc_o[8][4];
    #pragma unroll
    for (int nt = 0; nt < 8; nt++)
        #pragma unroll
        for (int r = 0; r < 4; r++) acc_o[nt][r] = 0.f;

    const int i0 = qs + w * 16 + g;
    const int kc_start = (qs >= WIN) ? (qs - WIN) : 0;

    for (int kc = kc_start; kc <= qs; kc += 64) {
        #pragma unroll
        for (int it = 0; it < 16; it++) {
            int c   = tid + it * 128;
            int arr = c >> 9;
            int rem = c & 511;
            int row = rem >> 3;
            int col = (rem & 7) * 8;
            const __nv_bfloat16* src =
                (arr == 0 ? g_kh : arr == 1 ? g_kl : arr == 2 ? g_vh : g_vl)
                + base + (size_t)(kc + row) * DK + col;
            unsigned dst = (arr < 2) ? smem_u32(&Ks[arr][row][col])
                                     : smem_u32(&Vs[arr - 2][row][col]);
            CP_ASYNC16(dst, src);
        }
        CP_COMMIT();
        asm volatile("cp.async.wait_group 0;\n" ::: "memory");
        __syncthreads();

        float s[8][4];
        #pragma unroll
        for (int nt = 0; nt < 8; nt++)
            #pragma unroll
            for (int r = 0; r < 4; r++) s[nt][r] = 0.f;

        #pragma unroll
        for (int kt = 0; kt < 4; kt++) {
            #pragma unroll
            for (int nc = 0; nc < 4; nc++) {
                uint32_t kh[4], kl[4];
                ldsm4(smem_u32(&Ks[0][nc * 16 + kb_nrow][kt * 16 + kb_kcol]), kh);
                ldsm4(smem_u32(&Ks[1][nc * 16 + kb_nrow][kt * 16 + kb_kcol]), kl);
                float* s0 = s[2 * nc];
                float* s1 = s[2 * nc + 1];
                // interleave the two chains (distance 2)
                mma16816(s0, qa[0][kt], kh[0], kh[2]);
                mma16816(s1, qa[0][kt], kh[1], kh[3]);
                mma16816(s0, qa[0][kt], kl[0], kl[2]);
                mma16816(s1, qa[0][kt], kl[1], kl[3]);
                mma16816(s0, qa[1][kt], kh[0], kh[2]);
                mma16816(s1, qa[1][kt], kh[1], kh[3]);
            }
        }

        if (kc == qs || kc + WIN == qs) {
            #pragma unroll
            for (int nt = 0; nt < 8; nt++) {
                int jb = kc + nt * 8 + tig * 2;
                #pragma unroll
                for (int r = 0; r < 4; r++) {
                    int j = jb + (r & 1);
                    int i = i0 + ((r >= 2) ? 8 : 0);
                    if (j > i || j < i - WIN) s[nt][r] = -1e30f;
                }
            }
        }

        float t0 = -1e30f, t1 = -1e30f;
        #pragma unroll
        for (int nt = 0; nt < 8; nt++) {
            t0 = fmaxf(t0, fmaxf(s[nt][0], s[nt][1]));
            t1 = fmaxf(t1, fmaxf(s[nt][2], s[nt][3]));
        }
        t0 = fmaxf(t0, __shfl_xor_sync(0xffffffffu, t0, 1));
        t0 = fmaxf(t0, __shfl_xor_sync(0xffffffffu, t0, 2));
        t1 = fmaxf(t1, __shfl_xor_sync(0xffffffffu, t1, 1));
        t1 = fmaxf(t1, __shfl_xor_sync(0xffffffffu, t1, 2));

        float mn0 = fmaxf(m0, t0), mn1 = fmaxf(m1, t1);
        float corr0 = __expf(m0 - mn0), corr1 = __expf(m1 - mn1);
        m0 = mn0; m1 = mn1;

        uint32_t ph[4][4], pl[4][4];
        float suml0 = 0.f, suml1 = 0.f;
        #pragma unroll
        for (int kt = 0; kt < 4; kt++) {
            #pragma unroll
            for (int half = 0; half < 2; half++) {
                int nt = 2 * kt + half;
                float p0 = __expf(s[nt][0] - m0);
                float p1 = __expf(s[nt][1] - m0);
                float p2 = __expf(s[nt][2] - m1);
                float p3 = __expf(s[nt][3] - m1);
                suml0 += p0 + p1;
                suml1 += p2 + p3;
                __nv_bfloat16 h0 = __float2bfloat16_rn(p0), h1 = __float2bfloat16_rn(p1);
                __nv_bfloat16 h2 = __float2bfloat16_rn(p2), h3 = __float2bfloat16_rn(p3);
                ph[kt][half * 2 + 0] = packbf(h0, h1);
                ph[kt][half * 2 + 1] = packbf(h2, h3);
                pl[kt][half * 2 + 0] = packbf(
                    __float2bfloat16_rn(p0 - __bfloat162float(h0)),
                    __float2bfloat16_rn(p1 - __bfloat162float(h1)));
                pl[kt][half * 2 + 1] = packbf(
                    __float2bfloat16_rn(p2 - __bfloat162float(h2)),
                    __float2bfloat16_rn(p3 - __bfloat162float(h3)));
            }
        }
        l0 = l0 * corr0 + suml0;
        l1 = l1 * corr1 + suml1;

        #pragma unroll
        for (int nt = 0; nt < 8; nt++) {
            acc_o[nt][0] *= corr0;
            acc_o[nt][1] *= corr0;
            acc_o[nt][2] *= corr1;
            acc_o[nt][3] *= corr1;
        }

        #pragma unroll
        for (int kt = 0; kt < 4; kt++) {
            #pragma unroll
            for (int nc = 0; nc < 4; nc++) {
                uint32_t vh[4], vl[4];
                ldsm4t(smem_u32(&Vs[0][kt * 16 + vb_krow][nc * 16 + vb_noff]), vh);
                ldsm4t(smem_u32(&Vs[1][kt * 16 + vb_krow][nc * 16 + vb_noff]), vl);
                float* o0 = acc_o[2 * nc];
                float* o1 = acc_o[2 * nc + 1];
                // interleave the two chains (distance 2)
                mma16816(o0, ph[kt], vh[0], vh[1]);
                mma16816(o1, ph[kt], vh[2], vh[3]);
                mma16816(o0, pl[kt], vh[0], vh[1]);
                mma16816(o1, pl[kt], vh[2], vh[3]);
                mma16816(o0, ph[kt], vl[0], vl[1]);
                mma16816(o1, ph[kt], vl[2], vl[3]);
            }
        }
        __syncthreads();
    }

    l0 += __shfl_xor_sync(0xffffffffu, l0, 1);
    l0 += __shfl_xor_sync(0xffffffffu, l0, 2);
    l1 += __shfl_xor_sync(0xffffffffu, l1, 1);
    l1 += __shfl_xor_sync(0xffffffffu, l1, 2);
    float inv0 = 1.f / l0, inv1 = 1.f / l1;

    size_t r0off = ((size_t)(bb * S_ + i0)) * DM + h * DK;
    size_t r1off = r0off + (size_t)8 * DM;
    #pragma unroll
    for (int nt = 0; nt < 8; nt++) {
        int d = nt * 8 + tig * 2;
        store_split(g_ah, g_al, r0off + d, acc_o[nt][0] * inv0, acc_o[nt][1] * inv0);
        store_split(g_ah, g_al, r1off + d, acc_o[nt][2] * inv1, acc_o[nt][3] * inv1);
    }
}

// ---------------------------------------------------------------------------
extern "C" void kernel_launch(void* const* d_in, const int* in_sizes, int n_in,
                              void* d_out, int out_size) {
    const float* x     = (const float*)d_in[0];   // [2,2048,1024]
    const float* w_qkv = (const float*)d_in[1];   // [1024,3072]
    const float* w_o   = (const float*)d_in[2];   // [1024,1024]
    float* out = (float*)d_out;                   // [2,2048,1024]

    __nv_bfloat16 *xh, *xl, *wqh, *wql, *woh, *wol;
    cudaGetSymbolAddress((void**)&xh,  g_xh);
    cudaGetSymbolAddress((void**)&xl,  g_xl);
    cudaGetSymbolAddress((void**)&wqh, g_wqh);
    cudaGetSymbolAddress((void**)&wql, g_wql);
    cudaGetSymbolAddress((void**)&woh, g_woh);
    cudaGetSymbolAddress((void**)&wol, g_wol);

    // 0) hi/lo bf16 splits of x and weights
    split_kernel<<<MTOT * DM / 1024, 256>>>(x, xh, xl, MTOT * DM);
    split_kernel<<<DM * 3 * DM / 1024, 256>>>(w_qkv, wqh, wql, DM * 3 * DM);
    split_kernel<<<DM * DM / 1024, 256>>>(w_o, woh, wol, DM * DM);

    // 1) QKV projection (tensor core) + RoPE + bf16 hi/lo q/k/v
    {
        dim3 grid(3 * DM / BN, MTOT / BM);   // (24, 32)
        qkv_mma_rope<<<grid, 256>>>();
    }
    // 2) Sliding-window attention (tensor core), writes g_ah/g_al
    {
        dim3 grid(S_ / 64, NH, B_);          // (32, 16, 2)
        attn_mma<<<grid, 128>>>();
    }
    // 3) Output projection (tensor core)
    {
        dim3 grid(DM / BN, MTOT / BM);       // (8, 32)
        oproj_mma<<<grid, 256>>>(out);
    }
}